// round 1
// baseline (speedup 1.0000x reference)
#include <cuda_runtime.h>
#include <cstdint>

// ---------------------------------------------------------------------------
// TemplatePointwiseAttention, restructured:
//   P[c][n]  = (1/sqrt(32)) * sum_d wq[c, h*32+d] * wk[ct, h*32+d],  n = h*64+ct
//   Wf[n][c2]=               sum_d wv[ct, h*32+d] * wo[h*32+d, c2]
//   L   = z @ P                      (GEMM1, per-pixel [128]->[256])
//   logits[h,t] = sum_ct L[h*64+ct] * t[t,p,ct]  (+ mask bias)
//   attn = softmax_t(logits)
//   M2[n] = sum_t attn[h,t] * t[t,p,ct]
//   out  = M2 @ Wf + bo              (GEMM2, per-pixel [256]->[128])
// ---------------------------------------------------------------------------

#define NT 4
#define CT 64
#define CZ 128
#define NP 256           // H*CT
#define TP 64            // pixels per block
#define NPIX (512*512)
#define INF_ 100000.0f

__device__ float g_P [CZ * NP];   // [c][n]
__device__ float g_Wf[NP * CZ];   // [n][c2]

typedef unsigned long long u64;

__device__ __forceinline__ u64 pk2(float lo, float hi) {
    u64 r; asm("mov.b64 %0, {%1,%2};" : "=l"(r) : "f"(lo), "f"(hi)); return r;
}
__device__ __forceinline__ void upk2(float& lo, float& hi, u64 v) {
    asm("mov.b64 {%0,%1}, %2;" : "=f"(lo), "=f"(hi) : "l"(v));
}
// packed 2-wide fp32 FMA (sm_100+): d = a*b + d  (elementwise on 2 lanes)
#define FMA2(d, a, b) asm("fma.rn.f32x2 %0, %1, %2, %0;" : "+l"(d) : "l"(a), "l"(b))

// ---------------------------------------------------------------------------
// Precompute fused weight matrices (tiny: 65536 dots of length 32)
// ---------------------------------------------------------------------------
__global__ void precompute_kernel(const float* __restrict__ wq,
                                  const float* __restrict__ wk,
                                  const float* __restrict__ wv,
                                  const float* __restrict__ wo) {
    int idx = blockIdx.x * blockDim.x + threadIdx.x;
    const float invs = 0.17677669529663689f;  // 1/sqrt(32)
    if (idx < CZ * NP) {
        int c = idx >> 8;          // 0..127
        int n = idx & 255;
        int h = n >> 6, ct = n & 63;
        float sum = 0.f;
#pragma unroll
        for (int d = 0; d < 32; d++)
            sum += wq[c * CZ + h * 32 + d] * wk[ct * CZ + h * 32 + d];
        g_P[c * NP + n] = sum * invs;
    } else {
        int j = idx - CZ * NP;     // 0..32767
        int n = j >> 7;
        int c2 = j & 127;
        int h = n >> 6, ct = n & 63;
        float sum = 0.f;
#pragma unroll
        for (int d = 0; d < 32; d++)
            sum += wv[ct * CZ + h * 32 + d] * wo[(h * 32 + d) * CZ + c2];
        g_Wf[n * CZ + c2] = sum;
    }
}

// ---------------------------------------------------------------------------
// Fused main kernel
// ---------------------------------------------------------------------------
struct Smem {
    float zsh[TP][CZ];          // 32 KB  z tile (pixel-major)
    float tsh[NT][TP][CT];      // 64 KB  t tile
    float Lsh[TP][NP];          // 64 KB  L, later overwritten by M2
    union {
        float psh[16][NP];      // 16 KB  P k-chunk
        float wfsh[32][CZ];     // 16 KB  Wf k-chunk
    } u;
    float mask[NT];
};

__global__ void __launch_bounds__(256, 1)
attn_kernel(const float* __restrict__ t, const float* __restrict__ z,
            const float* __restrict__ tmask, const float* __restrict__ bo,
            float* __restrict__ out) {
    extern __shared__ char smraw[];
    Smem* s = reinterpret_cast<Smem*>(smraw);
    const int tid = threadIdx.x;
    const int tx = tid & 31;          // n/c2 tile index (lane)
    const int ty = tid >> 5;          // pixel-group (warp)
    const int P0 = blockIdx.x * TP;

    // ---- stage z, t, mask into smem (coalesced float4) ----
    {
        const float4* zsrc = reinterpret_cast<const float4*>(z + (size_t)P0 * CZ);
        float4* zdst = reinterpret_cast<float4*>(&s->zsh[0][0]);
#pragma unroll
        for (int i = 0; i < 8; i++) zdst[i * 256 + tid] = zsrc[i * 256 + tid];
#pragma unroll
        for (int tt = 0; tt < NT; tt++) {
            const float4* tsrc = reinterpret_cast<const float4*>(
                t + (size_t)tt * NPIX * CT + (size_t)P0 * CT);
            float4* tdst = reinterpret_cast<float4*>(&s->tsh[tt][0][0]);
#pragma unroll
            for (int i = 0; i < 4; i++) tdst[i * 256 + tid] = tsrc[i * 256 + tid];
        }
        if (tid < NT) s->mask[tid] = tmask[tid];
    }

    // ---- GEMM1: Lsh[64][256] = zsh[64][128] @ P[128][256] ----
    // thread tile: 8 pixels (ty*8+i) x 8 n (tx*8+j), f32x2 accumulators
    u64 acc[8][4];
#pragma unroll
    for (int i = 0; i < 8; i++)
#pragma unroll
        for (int j = 0; j < 4; j++) acc[i][j] = 0ULL;

    for (int kc = 0; kc < CZ; kc += 16) {
        __syncthreads();
        {
            const float4* ps = reinterpret_cast<const float4*>(g_P + kc * NP);
            float4* pd = reinterpret_cast<float4*>(&s->u.psh[0][0]);
#pragma unroll
            for (int i = 0; i < 4; i++) pd[i * 256 + tid] = ps[i * 256 + tid];
        }
        __syncthreads();
#pragma unroll
        for (int k = 0; k < 16; k++) {
            ulonglong2 p01 = *reinterpret_cast<const ulonglong2*>(&s->u.psh[k][tx * 8]);
            ulonglong2 p23 = *reinterpret_cast<const ulonglong2*>(&s->u.psh[k][tx * 8 + 4]);
#pragma unroll
            for (int i = 0; i < 8; i++) {
                float zv = s->zsh[ty * 8 + i][kc + k];
                u64 zz = pk2(zv, zv);
                FMA2(acc[i][0], zz, p01.x);
                FMA2(acc[i][1], zz, p01.y);
                FMA2(acc[i][2], zz, p23.x);
                FMA2(acc[i][3], zz, p23.y);
            }
        }
    }

    // ---- write L to smem (warp-private rows) ----
#pragma unroll
    for (int i = 0; i < 8; i++) {
        float a0, a1, a2, a3, a4, a5, a6, a7;
        upk2(a0, a1, acc[i][0]); upk2(a2, a3, acc[i][1]);
        upk2(a4, a5, acc[i][2]); upk2(a6, a7, acc[i][3]);
        float4* row = reinterpret_cast<float4*>(&s->Lsh[ty * 8 + i][0]);
        row[tx * 2 + 0] = make_float4(a0, a1, a2, a3);
        row[tx * 2 + 1] = make_float4(a4, a5, a6, a7);
    }
    __syncwarp();

    // ---- per-pixel attention epilogue (warp handles its 8 pixels) ----
#pragma unroll 1
    for (int i = 0; i < 8; i++) {
        const int p = ty * 8 + i;
        float attn = 0.f;
        if (tx < 16) {
            const int h = tx >> 2, tt = tx & 3;
            const float* Lr = &s->Lsh[p][h * CT];
            const float* Tr = &s->tsh[tt][p][0];
            float lg = 0.f;
#pragma unroll
            for (int ct = 0; ct < CT; ct++) lg += Lr[ct] * Tr[ct];
            lg += INF_ * (s->mask[tt] - 1.0f);
            float m = lg;
            m = fmaxf(m, __shfl_xor_sync(0xFFFFu, m, 1));
            m = fmaxf(m, __shfl_xor_sync(0xFFFFu, m, 2));
            float e = __expf(lg - m);
            float sum = e;
            sum += __shfl_xor_sync(0xFFFFu, sum, 1);
            sum += __shfl_xor_sync(0xFFFFu, sum, 2);
            attn = e / sum;
        }
        __syncwarp();
        // broadcast the 4 attn weights for this lane's head (h = n>>6 = tx>>3)
        const int hb = (tx >> 3) * 4;
        float a0 = __shfl_sync(0xFFFFFFFFu, attn, hb + 0);
        float a1 = __shfl_sync(0xFFFFFFFFu, attn, hb + 1);
        float a2 = __shfl_sync(0xFFFFFFFFu, attn, hb + 2);
        float a3 = __shfl_sync(0xFFFFFFFFu, attn, hb + 3);
        // M2[n] for n = tx*8 .. tx*8+7  (ct = n & 63)
        const int ctb = (tx * 8) & 63;
        float4 t0a = *reinterpret_cast<const float4*>(&s->tsh[0][p][ctb]);
        float4 t0b = *reinterpret_cast<const float4*>(&s->tsh[0][p][ctb + 4]);
        float4 t1a = *reinterpret_cast<const float4*>(&s->tsh[1][p][ctb]);
        float4 t1b = *reinterpret_cast<const float4*>(&s->tsh[1][p][ctb + 4]);
        float4 t2a = *reinterpret_cast<const float4*>(&s->tsh[2][p][ctb]);
        float4 t2b = *reinterpret_cast<const float4*>(&s->tsh[2][p][ctb + 4]);
        float4 t3a = *reinterpret_cast<const float4*>(&s->tsh[3][p][ctb]);
        float4 t3b = *reinterpret_cast<const float4*>(&s->tsh[3][p][ctb + 4]);
        float4 m2a, m2b;
        m2a.x = a0 * t0a.x + a1 * t1a.x + a2 * t2a.x + a3 * t3a.x;
        m2a.y = a0 * t0a.y + a1 * t1a.y + a2 * t2a.y + a3 * t3a.y;
        m2a.z = a0 * t0a.z + a1 * t1a.z + a2 * t2a.z + a3 * t3a.z;
        m2a.w = a0 * t0a.w + a1 * t1a.w + a2 * t2a.w + a3 * t3a.w;
        m2b.x = a0 * t0b.x + a1 * t1b.x + a2 * t2b.x + a3 * t3b.x;
        m2b.y = a0 * t0b.y + a1 * t1b.y + a2 * t2b.y + a3 * t3b.y;
        m2b.z = a0 * t0b.z + a1 * t1b.z + a2 * t2b.z + a3 * t3b.z;
        m2b.w = a0 * t0b.w + a1 * t1b.w + a2 * t2b.w + a3 * t3b.w;
        float4* Ld = reinterpret_cast<float4*>(&s->Lsh[p][tx * 8]);
        Ld[0] = m2a;
        Ld[1] = m2b;
        __syncwarp();
    }

    __syncthreads();   // M2 done everywhere; psh free for wfsh reuse

    // ---- GEMM2: out[64][128] = M2[64][256] @ Wf[256][128] + bo ----
    // thread tile: 8 pixels (ty*8+i) x 4 c2 (tx*4+j)
    u64 acc2[8][2];
#pragma unroll
    for (int i = 0; i < 8; i++) { acc2[i][0] = 0ULL; acc2[i][1] = 0ULL; }

    for (int kc = 0; kc < NP; kc += 32) {
        __syncthreads();
        {
            const float4* ws = reinterpret_cast<const float4*>(g_Wf + kc * CZ);
            float4* wd = reinterpret_cast<float4*>(&s->u.wfsh[0][0]);
#pragma unroll
            for (int i = 0; i < 4; i++) wd[i * 256 + tid] = ws[i * 256 + tid];
        }
        __syncthreads();
#pragma unroll
        for (int k = 0; k < 32; k++) {
            ulonglong2 ww = *reinterpret_cast<const ulonglong2*>(&s->u.wfsh[k][tx * 4]);
#pragma unroll
            for (int i = 0; i < 8; i++) {
                float mv = s->Lsh[ty * 8 + i][kc + k];
                u64 mm = pk2(mv, mv);
                FMA2(acc2[i][0], mm, ww.x);
                FMA2(acc2[i][1], mm, ww.y);
            }
        }
    }

    // ---- epilogue: add bias, write out ----
    float4 bov = *reinterpret_cast<const float4*>(bo + tx * 4);
#pragma unroll
    for (int i = 0; i < 8; i++) {
        float o0, o1, o2, o3;
        upk2(o0, o1, acc2[i][0]);
        upk2(o2, o3, acc2[i][1]);
        float4 v = make_float4(o0 + bov.x, o1 + bov.y, o2 + bov.z, o3 + bov.w);
        *reinterpret_cast<float4*>(out + (size_t)(P0 + ty * 8 + i) * CZ + tx * 4) = v;
    }
}

// ---------------------------------------------------------------------------
extern "C" void kernel_launch(void* const* d_in, const int* in_sizes, int n_in,
                              void* d_out, int out_size) {
    const float* t     = (const float*)d_in[0];
    const float* z     = (const float*)d_in[1];
    const float* tmask = (const float*)d_in[2];
    const float* wq    = (const float*)d_in[3];
    const float* wk    = (const float*)d_in[4];
    const float* wv    = (const float*)d_in[5];
    const float* wo    = (const float*)d_in[6];
    const float* bo    = (const float*)d_in[7];
    float* out = (float*)d_out;

    cudaFuncSetAttribute(attn_kernel, cudaFuncAttributeMaxDynamicSharedMemorySize,
                         (int)sizeof(Smem));

    precompute_kernel<<<(CZ * NP + NP * CZ) / 256, 256>>>(wq, wk, wv, wo);
    attn_kernel<<<NPIX / TP, 256, sizeof(Smem)>>>(t, z, tmask, bo, out);
}

// round 2
// speedup vs baseline: 1.1220x; 1.1220x over previous
#include <cuda_runtime.h>
#include <cstdint>

// ---------------------------------------------------------------------------
// TemplatePointwiseAttention, restructured:
//   P[c][n]  = (1/sqrt(32)) * sum_d wq[c, h*32+d] * wk[ct, h*32+d],  n = h*64+ct
//   Wf[n][c2]=               sum_d wv[ct, h*32+d] * wo[h*32+d, c2]
//   L   = z @ P                      (GEMM1, per-pixel [128]->[256])
//   logits[h,t] = sum_ct L[h*64+ct] * t[t,p,ct]  (+ mask bias)
//   attn = softmax_t(logits)
//   M2[n] = sum_t attn[h,t] * t[t,p,ct]
//   out  = M2 @ Wf + bo              (GEMM2, per-pixel [256]->[128])
//
// R2: conflict-free lane tiling (n in {4tx, 128+4tx}), float4 broadcast loads,
//     double-buffered weight chunks, vectorized+rotated logits dot.
// ---------------------------------------------------------------------------

#define NT 4
#define CT 64
#define CZ 128
#define NP 256           // H*CT
#define TP 64            // pixels per block
#define NPIX (512*512)
#define INF_ 100000.0f

__device__ float g_P [CZ * NP];   // [c][n]
__device__ float g_Wf[NP * CZ];   // [n][c2]

typedef unsigned long long u64;

__device__ __forceinline__ u64 pk2(float lo, float hi) {
    u64 r; asm("mov.b64 %0, {%1,%2};" : "=l"(r) : "f"(lo), "f"(hi)); return r;
}
__device__ __forceinline__ void upk2(float& lo, float& hi, u64 v) {
    asm("mov.b64 {%0,%1}, %2;" : "=f"(lo), "=f"(hi) : "l"(v));
}
// packed 2-wide fp32 FMA (sm_100+): d = a*b + d
#define FMA2(d, a, b) asm("fma.rn.f32x2 %0, %1, %2, %0;" : "+l"(d) : "l"(a), "l"(b))

// ---------------------------------------------------------------------------
__global__ void precompute_kernel(const float* __restrict__ wq,
                                  const float* __restrict__ wk,
                                  const float* __restrict__ wv,
                                  const float* __restrict__ wo) {
    int idx = blockIdx.x * blockDim.x + threadIdx.x;
    const float invs = 0.17677669529663689f;  // 1/sqrt(32)
    if (idx < CZ * NP) {
        int c = idx >> 8;
        int n = idx & 255;
        int h = n >> 6, ct = n & 63;
        float sum = 0.f;
#pragma unroll
        for (int d = 0; d < 32; d++)
            sum += wq[c * CZ + h * 32 + d] * wk[ct * CZ + h * 32 + d];
        g_P[c * NP + n] = sum * invs;
    } else {
        int j = idx - CZ * NP;
        int n = j >> 7;
        int c2 = j & 127;
        int h = n >> 6, ct = n & 63;
        float sum = 0.f;
#pragma unroll
        for (int d = 0; d < 32; d++)
            sum += wv[ct * CZ + h * 32 + d] * wo[(h * 32 + d) * CZ + c2];
        g_Wf[n * CZ + c2] = sum;
    }
}

// ---------------------------------------------------------------------------
struct Smem {
    float zsh[TP][CZ];          // 32 KB
    float tsh[NT][TP][CT];      // 64 KB
    float Lsh[TP][NP];          // 64 KB  (L, then M2)
    float wbuf[2][16 * NP];     // 2 x 16 KB double-buffered weight chunk
    float mask[NT];
};

__device__ __forceinline__ void copy_chunk(float* __restrict__ dst,
                                           const float* __restrict__ src, int tid) {
    const float4* s4 = reinterpret_cast<const float4*>(src);
    float4* d4 = reinterpret_cast<float4*>(dst);
#pragma unroll
    for (int i = 0; i < 4; i++) d4[i * 256 + tid] = s4[i * 256 + tid];
}

__global__ void __launch_bounds__(256, 1)
attn_kernel(const float* __restrict__ t, const float* __restrict__ z,
            const float* __restrict__ tmask, const float* __restrict__ bo,
            float* __restrict__ out) {
    extern __shared__ char smraw[];
    Smem* s = reinterpret_cast<Smem*>(smraw);
    const int tid = threadIdx.x;
    const int tx = tid & 31;          // lane: owns n in {4tx..4tx+3, 128+4tx..+3}
    const int ty = tid >> 5;          // warp: owns pixels ty*8 .. ty*8+7
    const int P0 = blockIdx.x * TP;

    // ---- stage z, t, mask (coalesced float4) ----
    {
        const float4* zsrc = reinterpret_cast<const float4*>(z + (size_t)P0 * CZ);
        float4* zdst = reinterpret_cast<float4*>(&s->zsh[0][0]);
#pragma unroll
        for (int i = 0; i < 8; i++) zdst[i * 256 + tid] = zsrc[i * 256 + tid];
#pragma unroll
        for (int tt = 0; tt < NT; tt++) {
            const float4* tsrc = reinterpret_cast<const float4*>(
                t + (size_t)tt * NPIX * CT + (size_t)P0 * CT);
            float4* tdst = reinterpret_cast<float4*>(&s->tsh[tt][0][0]);
#pragma unroll
            for (int i = 0; i < 4; i++) tdst[i * 256 + tid] = tsrc[i * 256 + tid];
        }
        if (tid < NT) s->mask[tid] = tmask[tid];
    }
    // prefetch weight chunk 0
    copy_chunk(s->wbuf[0], g_P, tid);
    __syncthreads();

    // ---- GEMM1: Lsh[64][256] = zsh[64][128] @ P[128][256] ----
    u64 acc[8][4];
#pragma unroll
    for (int i = 0; i < 8; i++)
#pragma unroll
        for (int j = 0; j < 4; j++) acc[i][j] = 0ULL;

#pragma unroll 1
    for (int c = 0; c < 8; c++) {
        const float* wb = s->wbuf[c & 1];
        if (c < 7) copy_chunk(s->wbuf[(c & 1) ^ 1], g_P + (c + 1) * 16 * NP, tid);
#pragma unroll
        for (int k4 = 0; k4 < 4; k4++) {
            float zf[8][4];
#pragma unroll
            for (int i = 0; i < 8; i++) {
                float4 v = *reinterpret_cast<const float4*>(&s->zsh[ty * 8 + i][c * 16 + k4 * 4]);
                zf[i][0] = v.x; zf[i][1] = v.y; zf[i][2] = v.z; zf[i][3] = v.w;
            }
#pragma unroll
            for (int kk = 0; kk < 4; kk++) {
                const float* wrow = wb + (k4 * 4 + kk) * NP;
                ulonglong2 pA = *reinterpret_cast<const ulonglong2*>(wrow + tx * 4);
                ulonglong2 pB = *reinterpret_cast<const ulonglong2*>(wrow + 128 + tx * 4);
#pragma unroll
                for (int i = 0; i < 8; i++) {
                    u64 zz = pk2(zf[i][kk], zf[i][kk]);
                    FMA2(acc[i][0], zz, pA.x);
                    FMA2(acc[i][1], zz, pA.y);
                    FMA2(acc[i][2], zz, pB.x);
                    FMA2(acc[i][3], zz, pB.y);
                }
            }
        }
        __syncthreads();
    }

    // ---- write L (warp-private rows) ----
#pragma unroll
    for (int i = 0; i < 8; i++) {
        float a0, a1, a2, a3, b0, b1, b2, b3;
        upk2(a0, a1, acc[i][0]); upk2(a2, a3, acc[i][1]);
        upk2(b0, b1, acc[i][2]); upk2(b2, b3, acc[i][3]);
        float4* row = reinterpret_cast<float4*>(&s->Lsh[ty * 8 + i][0]);
        row[tx]      = make_float4(a0, a1, a2, a3);   // n = 4tx..4tx+3
        row[32 + tx] = make_float4(b0, b1, b2, b3);   // n = 128+4tx..+3
    }
    __syncwarp();

    // ---- per-pixel attention epilogue ----
#pragma unroll 1
    for (int i = 0; i < 8; i++) {
        const int p = ty * 8 + i;
        float attn = 0.f;
        if (tx < 16) {
            const int h = tx >> 2, tt = tx & 3;
            const float* Lr = &s->Lsh[p][h * CT];
            const float* Tr = &s->tsh[tt][p][0];
            float4 av = make_float4(0.f, 0.f, 0.f, 0.f);
#pragma unroll
            for (int j = 0; j < 16; j++) {
                int ct = (tx * 4 + j * 4) & 63;       // start-offset rotation
                float4 lv = *reinterpret_cast<const float4*>(Lr + ct);
                float4 tv = *reinterpret_cast<const float4*>(Tr + ct);
                av.x += lv.x * tv.x; av.y += lv.y * tv.y;
                av.z += lv.z * tv.z; av.w += lv.w * tv.w;
            }
            float lg = (av.x + av.y) + (av.z + av.w);
            lg += INF_ * (s->mask[tt] - 1.0f);
            float m = lg;
            m = fmaxf(m, __shfl_xor_sync(0xFFFFu, m, 1));
            m = fmaxf(m, __shfl_xor_sync(0xFFFFu, m, 2));
            float e = __expf(lg - m);
            float sum = e;
            sum += __shfl_xor_sync(0xFFFFu, sum, 1);
            sum += __shfl_xor_sync(0xFFFFu, sum, 2);
            attn = e / sum;
        }
        __syncwarp();
        // heads for this lane's two n-groups: h0 = tx/16, h1 = 2 + tx/16
        const int hb0 = (tx >> 4) * 4;
        const int hb1 = hb0 + 8;
        float a00 = __shfl_sync(0xFFFFFFFFu, attn, hb0 + 0);
        float a01 = __shfl_sync(0xFFFFFFFFu, attn, hb0 + 1);
        float a02 = __shfl_sync(0xFFFFFFFFu, attn, hb0 + 2);
        float a03 = __shfl_sync(0xFFFFFFFFu, attn, hb0 + 3);
        float a10 = __shfl_sync(0xFFFFFFFFu, attn, hb1 + 0);
        float a11 = __shfl_sync(0xFFFFFFFFu, attn, hb1 + 1);
        float a12 = __shfl_sync(0xFFFFFFFFu, attn, hb1 + 2);
        float a13 = __shfl_sync(0xFFFFFFFFu, attn, hb1 + 3);
        // both n-groups share ct block (4tx)&63
        const int ctb = (tx * 4) & 63;
        float4 t0 = *reinterpret_cast<const float4*>(&s->tsh[0][p][ctb]);
        float4 t1 = *reinterpret_cast<const float4*>(&s->tsh[1][p][ctb]);
        float4 t2 = *reinterpret_cast<const float4*>(&s->tsh[2][p][ctb]);
        float4 t3 = *reinterpret_cast<const float4*>(&s->tsh[3][p][ctb]);
        float4 m0, m1;
        m0.x = a00 * t0.x + a01 * t1.x + a02 * t2.x + a03 * t3.x;
        m0.y = a00 * t0.y + a01 * t1.y + a02 * t2.y + a03 * t3.y;
        m0.z = a00 * t0.z + a01 * t1.z + a02 * t2.z + a03 * t3.z;
        m0.w = a00 * t0.w + a01 * t1.w + a02 * t2.w + a03 * t3.w;
        m1.x = a10 * t0.x + a11 * t1.x + a12 * t2.x + a13 * t3.x;
        m1.y = a10 * t0.y + a11 * t1.y + a12 * t2.y + a13 * t3.y;
        m1.z = a10 * t0.z + a11 * t1.z + a12 * t2.z + a13 * t3.z;
        m1.w = a10 * t0.w + a11 * t1.w + a12 * t2.w + a13 * t3.w;
        float4* Ld = reinterpret_cast<float4*>(&s->Lsh[p][0]);
        Ld[tx]      = m0;   // M2[4tx..]
        Ld[32 + tx] = m1;   // M2[128+4tx..]
        __syncwarp();
    }

    // GEMM2 chunk 0 prefetch; also guarantees all M2 writes visible (own rows only anyway)
    copy_chunk(s->wbuf[0], g_Wf, tid);
    __syncthreads();

    // ---- GEMM2: out[64][128] = M2[64][256] @ Wf[256][128] + bo ----
    u64 acc2[8][2];
#pragma unroll
    for (int i = 0; i < 8; i++) { acc2[i][0] = 0ULL; acc2[i][1] = 0ULL; }

#pragma unroll 1
    for (int c = 0; c < 8; c++) {
        const float* wb = s->wbuf[c & 1];
        if (c < 7) copy_chunk(s->wbuf[(c & 1) ^ 1], g_Wf + (c + 1) * 32 * CZ, tid);
#pragma unroll
        for (int k4 = 0; k4 < 8; k4++) {
            float mf[8][4];
#pragma unroll
            for (int i = 0; i < 8; i++) {
                float4 v = *reinterpret_cast<const float4*>(&s->Lsh[ty * 8 + i][c * 32 + k4 * 4]);
                mf[i][0] = v.x; mf[i][1] = v.y; mf[i][2] = v.z; mf[i][3] = v.w;
            }
#pragma unroll
            for (int kk = 0; kk < 4; kk++) {
                ulonglong2 ww = *reinterpret_cast<const ulonglong2*>(
                    wb + (k4 * 4 + kk) * CZ + tx * 4);
#pragma unroll
                for (int i = 0; i < 8; i++) {
                    u64 mm = pk2(mf[i][kk], mf[i][kk]);
                    FMA2(acc2[i][0], mm, ww.x);
                    FMA2(acc2[i][1], mm, ww.y);
                }
            }
        }
        __syncthreads();
    }

    // ---- epilogue: add bias, write out ----
    float4 bov = *reinterpret_cast<const float4*>(bo + tx * 4);
#pragma unroll
    for (int i = 0; i < 8; i++) {
        float o0, o1, o2, o3;
        upk2(o0, o1, acc2[i][0]);
        upk2(o2, o3, acc2[i][1]);
        float4 v = make_float4(o0 + bov.x, o1 + bov.y, o2 + bov.z, o3 + bov.w);
        *reinterpret_cast<float4*>(out + (size_t)(P0 + ty * 8 + i) * CZ + tx * 4) = v;
    }
}

// ---------------------------------------------------------------------------
extern "C" void kernel_launch(void* const* d_in, const int* in_sizes, int n_in,
                              void* d_out, int out_size) {
    const float* t     = (const float*)d_in[0];
    const float* z     = (const float*)d_in[1];
    const float* tmask = (const float*)d_in[2];
    const float* wq    = (const float*)d_in[3];
    const float* wk    = (const float*)d_in[4];
    const float* wv    = (const float*)d_in[5];
    const float* wo    = (const float*)d_in[6];
    const float* bo    = (const float*)d_in[7];
    float* out = (float*)d_out;

    cudaFuncSetAttribute(attn_kernel, cudaFuncAttributeMaxDynamicSharedMemorySize,
                         (int)sizeof(Smem));

    precompute_kernel<<<(CZ * NP + NP * CZ) / 256, 256>>>(wq, wk, wv, wo);
    attn_kernel<<<NPIX / TP, 256, sizeof(Smem)>>>(t, z, tmask, bo, out);
}

// round 3
// speedup vs baseline: 1.1259x; 1.0034x over previous
#include <cuda_runtime.h>
#include <cstdint>

// ---------------------------------------------------------------------------
// TemplatePointwiseAttention, restructured:
//   P[c][n]  = (1/sqrt(32)) * sum_d wq[c, h*32+d] * wk[ct, h*32+d],  n = h*64+ct
//   Wf[n][c2]=               sum_d wv[ct, h*32+d] * wo[h*32+d, c2]
//   L   = z @ P                      (GEMM1, per-pixel [128]->[256])
//   logits[h,t] = sum_ct L[h*64+ct] * t[t,p,ct]  (+ mask bias)
//   attn = softmax_t(logits)
//   M2[n] = sum_t attn[h,t] * t[t,p,ct]
//   out  = M2 @ Wf + bo              (GEMM2, per-pixel [256]->[128])
//
// R2: conflict-free lane tiling (n in {4tx, 128+4tx}), float4 broadcast loads,
//     double-buffered weight chunks, vectorized+rotated logits dot.
// ---------------------------------------------------------------------------

#define NT 4
#define CT 64
#define CZ 128
#define NP 256           // H*CT
#define TP 64            // pixels per block
#define NPIX (512*512)
#define INF_ 100000.0f

__device__ float g_P [CZ * NP];   // [c][n]
__device__ float g_Wf[NP * CZ];   // [n][c2]

typedef unsigned long long u64;

__device__ __forceinline__ u64 pk2(float lo, float hi) {
    u64 r; asm("mov.b64 %0, {%1,%2};" : "=l"(r) : "f"(lo), "f"(hi)); return r;
}
__device__ __forceinline__ void upk2(float& lo, float& hi, u64 v) {
    asm("mov.b64 {%0,%1}, %2;" : "=f"(lo), "=f"(hi) : "l"(v));
}
// packed 2-wide fp32 FMA (sm_100+): d = a*b + d
#define FMA2(d, a, b) asm("fma.rn.f32x2 %0, %1, %2, %0;" : "+l"(d) : "l"(a), "l"(b))

// ---------------------------------------------------------------------------
__global__ void precompute_kernel(const float* __restrict__ wq,
                                  const float* __restrict__ wk,
                                  const float* __restrict__ wv,
                                  const float* __restrict__ wo) {
    int idx = blockIdx.x * blockDim.x + threadIdx.x;
    const float invs = 0.17677669529663689f;  // 1/sqrt(32)
    if (idx < CZ * NP) {
        int c = idx >> 8;
        int n = idx & 255;
        int h = n >> 6, ct = n & 63;
        float sum = 0.f;
#pragma unroll
        for (int d = 0; d < 32; d++)
            sum += wq[c * CZ + h * 32 + d] * wk[ct * CZ + h * 32 + d];
        g_P[c * NP + n] = sum * invs;
    } else {
        int j = idx - CZ * NP;
        int n = j >> 7;
        int c2 = j & 127;
        int h = n >> 6, ct = n & 63;
        float sum = 0.f;
#pragma unroll
        for (int d = 0; d < 32; d++)
            sum += wv[ct * CZ + h * 32 + d] * wo[(h * 32 + d) * CZ + c2];
        g_Wf[n * CZ + c2] = sum;
    }
}

// ---------------------------------------------------------------------------
struct Smem {
    float zsh[TP][CZ];          // 32 KB
    float tsh[NT][TP][CT];      // 64 KB
    float Lsh[TP][NP];          // 64 KB  (L, then M2)
    float wbuf[2][16 * NP];     // 2 x 16 KB double-buffered weight chunk
    float mask[NT];
};

__device__ __forceinline__ void copy_chunk(float* __restrict__ dst,
                                           const float* __restrict__ src, int tid) {
    const float4* s4 = reinterpret_cast<const float4*>(src);
    float4* d4 = reinterpret_cast<float4*>(dst);
#pragma unroll
    for (int i = 0; i < 4; i++) d4[i * 256 + tid] = s4[i * 256 + tid];
}

__global__ void __launch_bounds__(256, 1)
attn_kernel(const float* __restrict__ t, const float* __restrict__ z,
            const float* __restrict__ tmask, const float* __restrict__ bo,
            float* __restrict__ out) {
    extern __shared__ char smraw[];
    Smem* s = reinterpret_cast<Smem*>(smraw);
    const int tid = threadIdx.x;
    const int tx = tid & 31;          // lane: owns n in {4tx..4tx+3, 128+4tx..+3}
    const int ty = tid >> 5;          // warp: owns pixels ty*8 .. ty*8+7
    const int P0 = blockIdx.x * TP;

    // ---- stage z, t, mask (coalesced float4) ----
    {
        const float4* zsrc = reinterpret_cast<const float4*>(z + (size_t)P0 * CZ);
        float4* zdst = reinterpret_cast<float4*>(&s->zsh[0][0]);
#pragma unroll
        for (int i = 0; i < 8; i++) zdst[i * 256 + tid] = zsrc[i * 256 + tid];
#pragma unroll
        for (int tt = 0; tt < NT; tt++) {
            const float4* tsrc = reinterpret_cast<const float4*>(
                t + (size_t)tt * NPIX * CT + (size_t)P0 * CT);
            float4* tdst = reinterpret_cast<float4*>(&s->tsh[tt][0][0]);
#pragma unroll
            for (int i = 0; i < 4; i++) tdst[i * 256 + tid] = tsrc[i * 256 + tid];
        }
        if (tid < NT) s->mask[tid] = tmask[tid];
    }
    // prefetch weight chunk 0
    copy_chunk(s->wbuf[0], g_P, tid);
    __syncthreads();

    // ---- GEMM1: Lsh[64][256] = zsh[64][128] @ P[128][256] ----
    u64 acc[8][4];
#pragma unroll
    for (int i = 0; i < 8; i++)
#pragma unroll
        for (int j = 0; j < 4; j++) acc[i][j] = 0ULL;

#pragma unroll 1
    for (int c = 0; c < 8; c++) {
        const float* wb = s->wbuf[c & 1];
        if (c < 7) copy_chunk(s->wbuf[(c & 1) ^ 1], g_P + (c + 1) * 16 * NP, tid);
#pragma unroll
        for (int k4 = 0; k4 < 4; k4++) {
            float zf[8][4];
#pragma unroll
            for (int i = 0; i < 8; i++) {
                float4 v = *reinterpret_cast<const float4*>(&s->zsh[ty * 8 + i][c * 16 + k4 * 4]);
                zf[i][0] = v.x; zf[i][1] = v.y; zf[i][2] = v.z; zf[i][3] = v.w;
            }
#pragma unroll
            for (int kk = 0; kk < 4; kk++) {
                const float* wrow = wb + (k4 * 4 + kk) * NP;
                ulonglong2 pA = *reinterpret_cast<const ulonglong2*>(wrow + tx * 4);
                ulonglong2 pB = *reinterpret_cast<const ulonglong2*>(wrow + 128 + tx * 4);
#pragma unroll
                for (int i = 0; i < 8; i++) {
                    u64 zz = pk2(zf[i][kk], zf[i][kk]);
                    FMA2(acc[i][0], zz, pA.x);
                    FMA2(acc[i][1], zz, pA.y);
                    FMA2(acc[i][2], zz, pB.x);
                    FMA2(acc[i][3], zz, pB.y);
                }
            }
        }
        __syncthreads();
    }

    // ---- write L (warp-private rows) ----
#pragma unroll
    for (int i = 0; i < 8; i++) {
        float a0, a1, a2, a3, b0, b1, b2, b3;
        upk2(a0, a1, acc[i][0]); upk2(a2, a3, acc[i][1]);
        upk2(b0, b1, acc[i][2]); upk2(b2, b3, acc[i][3]);
        float4* row = reinterpret_cast<float4*>(&s->Lsh[ty * 8 + i][0]);
        row[tx]      = make_float4(a0, a1, a2, a3);   // n = 4tx..4tx+3
        row[32 + tx] = make_float4(b0, b1, b2, b3);   // n = 128+4tx..+3
    }
    __syncwarp();

    // ---- per-pixel attention epilogue ----
#pragma unroll 1
    for (int i = 0; i < 8; i++) {
        const int p = ty * 8 + i;
        float attn = 0.f;
        if (tx < 16) {
            const int h = tx >> 2, tt = tx & 3;
            const float* Lr = &s->Lsh[p][h * CT];
            const float* Tr = &s->tsh[tt][p][0];
            float4 av = make_float4(0.f, 0.f, 0.f, 0.f);
#pragma unroll
            for (int j = 0; j < 16; j++) {
                int ct = (tx * 4 + j * 4) & 63;       // start-offset rotation
                float4 lv = *reinterpret_cast<const float4*>(Lr + ct);
                float4 tv = *reinterpret_cast<const float4*>(Tr + ct);
                av.x += lv.x * tv.x; av.y += lv.y * tv.y;
                av.z += lv.z * tv.z; av.w += lv.w * tv.w;
            }
            float lg = (av.x + av.y) + (av.z + av.w);
            lg += INF_ * (s->mask[tt] - 1.0f);
            float m = lg;
            m = fmaxf(m, __shfl_xor_sync(0xFFFFu, m, 1));
            m = fmaxf(m, __shfl_xor_sync(0xFFFFu, m, 2));
            float e = __expf(lg - m);
            float sum = e;
            sum += __shfl_xor_sync(0xFFFFu, sum, 1);
            sum += __shfl_xor_sync(0xFFFFu, sum, 2);
            attn = e / sum;
        }
        __syncwarp();
        // heads for this lane's two n-groups: h0 = tx/16, h1 = 2 + tx/16
        const int hb0 = (tx >> 4) * 4;
        const int hb1 = hb0 + 8;
        float a00 = __shfl_sync(0xFFFFFFFFu, attn, hb0 + 0);
        float a01 = __shfl_sync(0xFFFFFFFFu, attn, hb0 + 1);
        float a02 = __shfl_sync(0xFFFFFFFFu, attn, hb0 + 2);
        float a03 = __shfl_sync(0xFFFFFFFFu, attn, hb0 + 3);
        float a10 = __shfl_sync(0xFFFFFFFFu, attn, hb1 + 0);
        float a11 = __shfl_sync(0xFFFFFFFFu, attn, hb1 + 1);
        float a12 = __shfl_sync(0xFFFFFFFFu, attn, hb1 + 2);
        float a13 = __shfl_sync(0xFFFFFFFFu, attn, hb1 + 3);
        // both n-groups share ct block (4tx)&63
        const int ctb = (tx * 4) & 63;
        float4 t0 = *reinterpret_cast<const float4*>(&s->tsh[0][p][ctb]);
        float4 t1 = *reinterpret_cast<const float4*>(&s->tsh[1][p][ctb]);
        float4 t2 = *reinterpret_cast<const float4*>(&s->tsh[2][p][ctb]);
        float4 t3 = *reinterpret_cast<const float4*>(&s->tsh[3][p][ctb]);
        float4 m0, m1;
        m0.x = a00 * t0.x + a01 * t1.x + a02 * t2.x + a03 * t3.x;
        m0.y = a00 * t0.y + a01 * t1.y + a02 * t2.y + a03 * t3.y;
        m0.z = a00 * t0.z + a01 * t1.z + a02 * t2.z + a03 * t3.z;
        m0.w = a00 * t0.w + a01 * t1.w + a02 * t2.w + a03 * t3.w;
        m1.x = a10 * t0.x + a11 * t1.x + a12 * t2.x + a13 * t3.x;
        m1.y = a10 * t0.y + a11 * t1.y + a12 * t2.y + a13 * t3.y;
        m1.z = a10 * t0.z + a11 * t1.z + a12 * t2.z + a13 * t3.z;
        m1.w = a10 * t0.w + a11 * t1.w + a12 * t2.w + a13 * t3.w;
        float4* Ld = reinterpret_cast<float4*>(&s->Lsh[p][0]);
        Ld[tx]      = m0;   // M2[4tx..]
        Ld[32 + tx] = m1;   // M2[128+4tx..]
        __syncwarp();
    }

    // GEMM2 chunk 0 prefetch; also guarantees all M2 writes visible (own rows only anyway)
    copy_chunk(s->wbuf[0], g_Wf, tid);
    __syncthreads();

    // ---- GEMM2: out[64][128] = M2[64][256] @ Wf[256][128] + bo ----
    u64 acc2[8][2];
#pragma unroll
    for (int i = 0; i < 8; i++) { acc2[i][0] = 0ULL; acc2[i][1] = 0ULL; }

#pragma unroll 1
    for (int c = 0; c < 8; c++) {
        const float* wb = s->wbuf[c & 1];
        if (c < 7) copy_chunk(s->wbuf[(c & 1) ^ 1], g_Wf + (c + 1) * 32 * CZ, tid);
#pragma unroll
        for (int k4 = 0; k4 < 8; k4++) {
            float mf[8][4];
#pragma unroll
            for (int i = 0; i < 8; i++) {
                float4 v = *reinterpret_cast<const float4*>(&s->Lsh[ty * 8 + i][c * 32 + k4 * 4]);
                mf[i][0] = v.x; mf[i][1] = v.y; mf[i][2] = v.z; mf[i][3] = v.w;
            }
#pragma unroll
            for (int kk = 0; kk < 4; kk++) {
                ulonglong2 ww = *reinterpret_cast<const ulonglong2*>(
                    wb + (k4 * 4 + kk) * CZ + tx * 4);
#pragma unroll
                for (int i = 0; i < 8; i++) {
                    u64 mm = pk2(mf[i][kk], mf[i][kk]);
                    FMA2(acc2[i][0], mm, ww.x);
                    FMA2(acc2[i][1], mm, ww.y);
                }
            }
        }
        __syncthreads();
    }

    // ---- epilogue: add bias, write out ----
    float4 bov = *reinterpret_cast<const float4*>(bo + tx * 4);
#pragma unroll
    for (int i = 0; i < 8; i++) {
        float o0, o1, o2, o3;
        upk2(o0, o1, acc2[i][0]);
        upk2(o2, o3, acc2[i][1]);
        float4 v = make_float4(o0 + bov.x, o1 + bov.y, o2 + bov.z, o3 + bov.w);
        *reinterpret_cast<float4*>(out + (size_t)(P0 + ty * 8 + i) * CZ + tx * 4) = v;
    }
}

// ---------------------------------------------------------------------------
extern "C" void kernel_launch(void* const* d_in, const int* in_sizes, int n_in,
                              void* d_out, int out_size) {
    const float* t     = (const float*)d_in[0];
    const float* z     = (const float*)d_in[1];
    const float* tmask = (const float*)d_in[2];
    const float* wq    = (const float*)d_in[3];
    const float* wk    = (const float*)d_in[4];
    const float* wv    = (const float*)d_in[5];
    const float* wo    = (const float*)d_in[6];
    const float* bo    = (const float*)d_in[7];
    float* out = (float*)d_out;

    cudaFuncSetAttribute(attn_kernel, cudaFuncAttributeMaxDynamicSharedMemorySize,
                         (int)sizeof(Smem));

    precompute_kernel<<<(CZ * NP + NP * CZ) / 256, 256>>>(wq, wk, wv, wo);
    attn_kernel<<<NPIX / TP, 256, sizeof(Smem)>>>(t, z, tmask, bo, out);
}

// round 5
// speedup vs baseline: 1.3100x; 1.1635x over previous
#include <cuda_runtime.h>
#include <cuda_fp16.h>
#include <cstdint>

// ---------------------------------------------------------------------------
// TemplatePointwiseAttention via mma.sync.m16n8k16 fp16-split (3-pass) GEMMs.
//   P[c][n]  = invs * sum_d wq[c,h*32+d]*wk[ct,h*32+d],   n = h*64+ct
//   Wf[n][c2]=        sum_d wv[ct,h*32+d]*wo[h*32+d,c2]
//   L  = z @ P      (per CTA: [64 x 128] @ [128 x 256])
//   logits[h,t] = sum_ct L[64h+ct]*t[t,p,ct] + bias; attn = softmax_t
//   M2[n] = sum_t attn[h(n),t]*t[t,p,ct(n)]
//   out = M2 @ Wf + bo   ([64 x 256] @ [256 x 128])
// fp16 split: x = hi + lo; 3 passes hi*hi + hi*lo + lo*hi (fp32 accum).
// smem layout: hi/lo interleaved per half2-pair -> every frag piece = 1 LDS.64.
// ---------------------------------------------------------------------------

#define NPIX (512*512)
#define INF_ 100000.0f

// strides in halves
#define A1_STR 264
#define A2_STR 520
#define B_STR  136       // B1 khalf [256 n][2*64]
#define B2_STR 264       // B2 khalf [128 c2][2*128]
#define T_STR  136       // t [4][64][2*64]

// smem byte offsets
#define OFF_BO   0u
#define OFF_BIAS 512u
#define OFF_A    1024u                    // 64*520*2 = 66560
#define OFF_B    (OFF_A + 66560u)        // 256*136*2 = 69632
#define OFF_T    (OFF_B + 69632u)        // 4*64*136*2 = 69632
#define SMEM_TOTAL (OFF_T + 69632u)      // = 206848

__device__ __align__(16) __half g_Pil[256 * 256];   // [n][4*cpair]: hi0 hi1 lo0 lo1
__device__ __align__(16) __half g_Wil[128 * 512];   // [c2][4*npair]

__device__ __forceinline__ uint32_t packh2(__half a, __half b) {
    __half2 h = __halves2half2(a, b);
    return *reinterpret_cast<uint32_t*>(&h);
}
__device__ __forceinline__ void split2h(float x, float y, uint32_t& hi, uint32_t& lo) {
    __half hx = __float2half_rn(x), hy = __float2half_rn(y);
    hi = packh2(hx, hy);
    lo = packh2(__float2half_rn(x - __half2float(hx)),
                __float2half_rn(y - __half2float(hy)));
}
__device__ __forceinline__ void mma16816(float* d, uint32_t a0, uint32_t a1,
                                         uint32_t a2, uint32_t a3,
                                         uint32_t b0, uint32_t b1) {
    asm volatile(
        "mma.sync.aligned.m16n8k16.row.col.f32.f16.f16.f32 "
        "{%0,%1,%2,%3}, {%4,%5,%6,%7}, {%8,%9}, {%0,%1,%2,%3};"
        : "+f"(d[0]), "+f"(d[1]), "+f"(d[2]), "+f"(d[3])
        : "r"(a0), "r"(a1), "r"(a2), "r"(a3), "r"(b0), "r"(b1));
}

// ---------------------------------------------------------------------------
__global__ void precompute_kernel(const float* __restrict__ wq,
                                  const float* __restrict__ wk,
                                  const float* __restrict__ wv,
                                  const float* __restrict__ wo) {
    int g = blockIdx.x * blockDim.x + threadIdx.x;   // 0..32767
    const float invs = 0.17677669529663689f;         // 1/sqrt(32)
    if (g < 16384) {            // P^T [n][c]: n=g>>6, c-pair=g&63
        int n = g >> 6, j = g & 63;
        int h = n >> 6, ct = n & 63;
        float s0 = 0.f, s1 = 0.f;
#pragma unroll
        for (int d = 0; d < 32; d++) {
            float kv = wk[ct * 128 + h * 32 + d];
            s0 += wq[(2 * j) * 128 + h * 32 + d] * kv;
            s1 += wq[(2 * j + 1) * 128 + h * 32 + d] * kv;
        }
        uint32_t hi, lo;
        split2h(s0 * invs, s1 * invs, hi, lo);
        *reinterpret_cast<uint2*>(g_Pil + n * 256 + 4 * j) = make_uint2(hi, lo);
    } else {                    // Wf^T [c2][n]: c2=(g')>>7, n-pair=(g')&127
        int gg = g - 16384;
        int c2 = gg >> 7, j = gg & 127;
        int n0 = 2 * j, n1 = 2 * j + 1;
        int h = n0 >> 6;
        float s0 = 0.f, s1 = 0.f;
#pragma unroll
        for (int d = 0; d < 32; d++) {
            float ov = wo[(h * 32 + d) * 128 + c2];
            s0 += wv[(n0 & 63) * 128 + h * 32 + d] * ov;
            s1 += wv[(n1 & 63) * 128 + h * 32 + d] * ov;
        }
        uint32_t hi, lo;
        split2h(s0, s1, hi, lo);
        *reinterpret_cast<uint2*>(g_Wil + c2 * 512 + 4 * j) = make_uint2(hi, lo);
    }
}

// ---------------------------------------------------------------------------
__global__ void __launch_bounds__(256, 1)
attn_kernel(const float* __restrict__ tg, const float* __restrict__ z,
            const float* __restrict__ tmask, const float* __restrict__ bo,
            float* __restrict__ out) {
    extern __shared__ char sm[];
    float* s_bo   = reinterpret_cast<float*>(sm + OFF_BO);
    float* s_bias = reinterpret_cast<float*>(sm + OFF_BIAS);
    __half* sA = reinterpret_cast<__half*>(sm + OFF_A);
    __half* sB = reinterpret_cast<__half*>(sm + OFF_B);
    __half* sT = reinterpret_cast<__half*>(sm + OFF_T);

    const int tid = threadIdx.x;
    const int lane = tid & 31, w = tid >> 5;
    const int c4 = lane & 3, lr = lane >> 2;
    const int mi = w >> 2;          // row band: pixels mi*32 .. +32
    const int hd = w & 3;           // head (GEMM1 n-band) / c2-band (GEMM2)
    const int P0 = blockIdx.x * 64;

    // ---- stage: bo, bias, z->A1 split, t->split, B1 khalf0 ----
    if (tid < 32) reinterpret_cast<float4*>(s_bo)[tid] =
        reinterpret_cast<const float4*>(bo)[tid];
    if (tid < 4) s_bias[tid] = INF_ * (tmask[tid] - 1.0f);
    {
        const float4* z4 = reinterpret_cast<const float4*>(z + (size_t)P0 * 128);
#pragma unroll 2
        for (int e = tid; e < 2048; e += 256) {
            float4 v = z4[e];
            int pix = e >> 5, q = e & 31;
            uint32_t h0, l0, h1, l1;
            split2h(v.x, v.y, h0, l0);
            split2h(v.z, v.w, h1, l1);
            *reinterpret_cast<uint4*>(sA + pix * A1_STR + 8 * q) =
                make_uint4(h0, l0, h1, l1);
        }
        const float4* t4 = reinterpret_cast<const float4*>(tg);
#pragma unroll 2
        for (int e = tid; e < 4096; e += 256) {
            int tt = e >> 10, pix = (e >> 4) & 63, q = e & 15;
            float4 v = t4[(size_t)tt * NPIX * 16 + (size_t)(P0 + pix) * 16 + q];
            uint32_t h0, l0, h1, l1;
            split2h(v.x, v.y, h0, l0);
            split2h(v.z, v.w, h1, l1);
            *reinterpret_cast<uint4*>(sT + (tt * 64 + pix) * T_STR + 8 * q) =
                make_uint4(h0, l0, h1, l1);
        }
#pragma unroll 2
        for (int e = tid; e < 4096; e += 256) {
            int n = e >> 4, i = e & 15;
            *reinterpret_cast<uint4*>(sB + n * B_STR + i * 8) =
                *reinterpret_cast<const uint4*>(g_Pil + n * 256 + i * 8);
        }
    }
    __syncthreads();

    // ---- GEMM1: acc1[m'][n'][4] over [64 pix x 256 n], warp tile 32x64 ----
    float acc1[2][8][4] = {};
#pragma unroll 1
    for (int kh = 0; kh < 2; kh++) {
        if (kh == 1) {
            __syncthreads();
#pragma unroll 2
            for (int e = tid; e < 4096; e += 256) {
                int n = e >> 4, i = e & 15;
                *reinterpret_cast<uint4*>(sB + n * B_STR + i * 8) =
                    *reinterpret_cast<const uint4*>(g_Pil + n * 256 + 128 + i * 8);
            }
            __syncthreads();
        }
#pragma unroll
        for (int kk = 0; kk < 4; kk++) {
            const int ks = kh * 4 + kk;
            uint2 Bf[8][2];
#pragma unroll
            for (int np = 0; np < 8; np++) {
                const __half* bp = sB + (hd * 64 + np * 8 + lr) * B_STR + 4 * (kk * 8 + c4);
                Bf[np][0] = *reinterpret_cast<const uint2*>(bp);
                Bf[np][1] = *reinterpret_cast<const uint2*>(bp + 16);
            }
#pragma unroll
            for (int mp = 0; mp < 2; mp++) {
                const __half* ap = sA + (mi * 32 + mp * 16 + lr) * A1_STR + 4 * (ks * 8 + c4);
                uint2 u00 = *reinterpret_cast<const uint2*>(ap);
                uint2 u10 = *reinterpret_cast<const uint2*>(ap + 8 * A1_STR);
                uint2 u01 = *reinterpret_cast<const uint2*>(ap + 16);
                uint2 u11 = *reinterpret_cast<const uint2*>(ap + 8 * A1_STR + 16);
#pragma unroll
                for (int np = 0; np < 8; np++) {
                    mma16816(acc1[mp][np], u00.x, u10.x, u01.x, u11.x,
                             Bf[np][0].x, Bf[np][1].x);
                    mma16816(acc1[mp][np], u00.x, u10.x, u01.x, u11.x,
                             Bf[np][0].y, Bf[np][1].y);
                    mma16816(acc1[mp][np], u00.y, u10.y, u01.y, u11.y,
                             Bf[np][0].x, Bf[np][1].x);
                }
            }
        }
    }
    __syncthreads();   // all warps done reading A1 before A2 overwrites it

    // ---- epilogue: logits + softmax + M2 -> A2 (split, interleaved) ----
    float attn[4][4];
#pragma unroll
    for (int gq = 0; gq < 4; gq++) {
        const int mp = gq >> 1, a = gq & 1;
        const int r = mi * 32 + mp * 16 + 8 * a + lr;
        float lg[4];
#pragma unroll
        for (int tt = 0; tt < 4; tt++) {
            float part = 0.f;
#pragma unroll
            for (int np = 0; np < 8; np++) {
                uint2 u = *reinterpret_cast<const uint2*>(
                    sT + (tt * 64 + r) * T_STR + 4 * (np * 4 + c4));
                float2 fh = __half22float2(*reinterpret_cast<__half2*>(&u.x));
                float2 fl = __half22float2(*reinterpret_cast<__half2*>(&u.y));
                part += acc1[mp][np][2 * a]     * (fh.x + fl.x)
                      + acc1[mp][np][2 * a + 1] * (fh.y + fl.y);
            }
            part += __shfl_xor_sync(0xFFFFFFFFu, part, 1);
            part += __shfl_xor_sync(0xFFFFFFFFu, part, 2);
            lg[tt] = part + s_bias[tt];
        }
        float m = fmaxf(fmaxf(lg[0], lg[1]), fmaxf(lg[2], lg[3]));
        float e0 = __expf(lg[0] - m), e1 = __expf(lg[1] - m);
        float e2 = __expf(lg[2] - m), e3 = __expf(lg[3] - m);
        float inv = 1.f / (e0 + e1 + e2 + e3);
        attn[gq][0] = e0 * inv; attn[gq][1] = e1 * inv;
        attn[gq][2] = e2 * inv; attn[gq][3] = e3 * inv;
    }
#pragma unroll
    for (int gq = 0; gq < 4; gq++) {
        const int mp = gq >> 1, a = gq & 1;
        const int r = mi * 32 + mp * 16 + 8 * a + lr;
#pragma unroll
        for (int np = 0; np < 8; np++) {
            float m0 = 0.f, m1 = 0.f;
#pragma unroll
            for (int tt = 0; tt < 4; tt++) {
                uint2 u = *reinterpret_cast<const uint2*>(
                    sT + (tt * 64 + r) * T_STR + 4 * (np * 4 + c4));
                float2 fh = __half22float2(*reinterpret_cast<__half2*>(&u.x));
                float2 fl = __half22float2(*reinterpret_cast<__half2*>(&u.y));
                m0 += attn[gq][tt] * (fh.x + fl.x);
                m1 += attn[gq][tt] * (fh.y + fl.y);
            }
            uint32_t hi, lo;
            split2h(m0, m1, hi, lo);
            *reinterpret_cast<uint2*>(sA + r * A2_STR + 4 * (hd * 32 + np * 4 + c4)) =
                make_uint2(hi, lo);
        }
    }

    // ---- GEMM2: out[64 x 128] = M2[64 x 256] @ Wf, warp tile 32x32 ----
    float acc2[2][4][4] = {};
#pragma unroll 1
    for (int kh = 0; kh < 2; kh++) {
        __syncthreads();
#pragma unroll 2
        for (int e = tid; e < 4096; e += 256) {
            int cc = e >> 5, i = e & 31;
            *reinterpret_cast<uint4*>(sB + cc * B2_STR + i * 8) =
                *reinterpret_cast<const uint4*>(g_Wil + cc * 512 + kh * 256 + i * 8);
        }
        __syncthreads();
#pragma unroll
        for (int kk = 0; kk < 8; kk++) {
            const int ks = kh * 8 + kk;
            uint2 Bf[4][2];
#pragma unroll
            for (int np = 0; np < 4; np++) {
                const __half* bp = sB + (hd * 32 + np * 8 + lr) * B2_STR + 4 * (kk * 8 + c4);
                Bf[np][0] = *reinterpret_cast<const uint2*>(bp);
                Bf[np][1] = *reinterpret_cast<const uint2*>(bp + 16);
            }
#pragma unroll
            for (int mp = 0; mp < 2; mp++) {
                const __half* ap = sA + (mi * 32 + mp * 16 + lr) * A2_STR + 4 * (ks * 8 + c4);
                uint2 u00 = *reinterpret_cast<const uint2*>(ap);
                uint2 u10 = *reinterpret_cast<const uint2*>(ap + 8 * A2_STR);
                uint2 u01 = *reinterpret_cast<const uint2*>(ap + 16);
                uint2 u11 = *reinterpret_cast<const uint2*>(ap + 8 * A2_STR + 16);
#pragma unroll
                for (int np = 0; np < 4; np++) {
                    mma16816(acc2[mp][np], u00.x, u10.x, u01.x, u11.x,
                             Bf[np][0].x, Bf[np][1].x);
                    mma16816(acc2[mp][np], u00.x, u10.x, u01.x, u11.x,
                             Bf[np][0].y, Bf[np][1].y);
                    mma16816(acc2[mp][np], u00.y, u10.y, u01.y, u11.y,
                             Bf[np][0].x, Bf[np][1].x);
                }
            }
        }
    }

    // ---- output: add bias, STG.64 (quad-contiguous 32B sectors) ----
#pragma unroll
    for (int mp = 0; mp < 2; mp++)
#pragma unroll
        for (int a = 0; a < 2; a++) {
            const size_t r = (size_t)(P0 + mi * 32 + mp * 16 + 8 * a + lr);
#pragma unroll
            for (int np = 0; np < 4; np++) {
                const int col = hd * 32 + np * 8 + 2 * c4;
                float2 b = *reinterpret_cast<const float2*>(s_bo + col);
                float2 v;
                v.x = acc2[mp][np][2 * a]     + b.x;
                v.y = acc2[mp][np][2 * a + 1] + b.y;
                *reinterpret_cast<float2*>(out + r * 128 + col) = v;
            }
        }
}

// ---------------------------------------------------------------------------
extern "C" void kernel_launch(void* const* d_in, const int* in_sizes, int n_in,
                              void* d_out, int out_size) {
    const float* t     = (const float*)d_in[0];
    const float* z     = (const float*)d_in[1];
    const float* tmask = (const float*)d_in[2];
    const float* wq    = (const float*)d_in[3];
    const float* wk    = (const float*)d_in[4];
    const float* wv    = (const float*)d_in[5];
    const float* wo    = (const float*)d_in[6];
    const float* bo    = (const float*)d_in[7];
    float* out = (float*)d_out;

    cudaFuncSetAttribute(attn_kernel, cudaFuncAttributeMaxDynamicSharedMemorySize,
                         (int)SMEM_TOTAL);
    precompute_kernel<<<128, 256>>>(wq, wk, wv, wo);
    attn_kernel<<<NPIX / 64, 256, SMEM_TOTAL>>>(t, z, tmask, bo, out);
}

// round 6
// speedup vs baseline: 2.1532x; 1.6437x over previous
#include <cuda_runtime.h>
#include <cuda_fp16.h>
#include <cstdint>

// ---------------------------------------------------------------------------
// TemplatePointwiseAttention via mma.sync.m16n8k16 fp16-split (3-pass) GEMMs.
// R6: 512 threads / 16 warps, fp32 t in smem, cp.async double-buffered B,
//     all smem pitches = 8 words mod 32 (conflict-free LDS.64).
// Warp (mi,hd): mi = w>>2 row band (16 pixels), hd = w&3 col band.
//   GEMM1 warp tile 16x64 (exactly one head), GEMM2 warp tile 16x32.
// ---------------------------------------------------------------------------

#define NPIX (512*512)
#define INF_ 100000.0f

// smem byte layout
#define OFF_BO   0u
#define OFF_BIAS 512u
#define OFF_A    1024u
#define A1_PITCH 544u        // 272 halves = 136 words  (mod32 = 8)
#define A2_PITCH 1056u       // 528 halves = 264 words  (mod32 = 8)
#define OFF_B    68608u      // two 40960B buffers
#define B_BUF    40960u
#define B1_PITCH 160u        // 40 words (mod32 = 8)
#define B2_PITCH 288u        // 72 words (mod32 = 8)
#define OFF_T    150528u
#define T_PITCH  288u        // 72 floats*4B... = 72 words (mod32 = 8)
#define SMEM_TOTAL 224256u

__device__ __align__(16) __half g_Pil[256 * 256];   // [n][pair j: hi0 hi1 lo0 lo1]
__device__ __align__(16) __half g_Wil[128 * 512];   // [c2][pair j: hi0 hi1 lo0 lo1]

__device__ __forceinline__ uint32_t smem_u32(const void* p) {
    uint32_t a;
    asm("{ .reg .u64 t; cvta.to.shared.u64 t, %1; cvt.u32.u64 %0, t; }" : "=r"(a) : "l"(p));
    return a;
}
__device__ __forceinline__ uint32_t packh2(__half a, __half b) {
    __half2 h = __halves2half2(a, b);
    return *reinterpret_cast<uint32_t*>(&h);
}
__device__ __forceinline__ void split2h(float x, float y, uint32_t& hi, uint32_t& lo) {
    __half hx = __float2half_rn(x), hy = __float2half_rn(y);
    hi = packh2(hx, hy);
    lo = packh2(__float2half_rn(x - __half2float(hx)),
                __float2half_rn(y - __half2float(hy)));
}
__device__ __forceinline__ void mma16816(float* d, uint32_t a0, uint32_t a1,
                                         uint32_t a2, uint32_t a3,
                                         uint32_t b0, uint32_t b1) {
    asm volatile(
        "mma.sync.aligned.m16n8k16.row.col.f32.f16.f16.f32 "
        "{%0,%1,%2,%3}, {%4,%5,%6,%7}, {%8,%9}, {%0,%1,%2,%3};"
        : "+f"(d[0]), "+f"(d[1]), "+f"(d[2]), "+f"(d[3])
        : "r"(a0), "r"(a1), "r"(a2), "r"(a3), "r"(b0), "r"(b1));
}
__device__ __forceinline__ void cp16(uint32_t dst, const void* src) {
    asm volatile("cp.async.cg.shared.global [%0], [%1], 16;" :: "r"(dst), "l"(src));
}
#define CP_COMMIT() asm volatile("cp.async.commit_group;" ::: "memory")
#define CP_WAIT0()  asm volatile("cp.async.wait_group 0;" ::: "memory")

// ---------------------------------------------------------------------------
__global__ void precompute_kernel(const float* __restrict__ wq,
                                  const float* __restrict__ wk,
                                  const float* __restrict__ wv,
                                  const float* __restrict__ wo) {
    int g = blockIdx.x * blockDim.x + threadIdx.x;   // 0..32767
    const float invs = 0.17677669529663689f;         // 1/sqrt(32)
    if (g < 16384) {            // P^T [n][c]
        int n = g >> 6, j = g & 63;
        int h = n >> 6, ct = n & 63;
        float s0 = 0.f, s1 = 0.f;
#pragma unroll
        for (int d = 0; d < 32; d++) {
            float kv = wk[ct * 128 + h * 32 + d];
            s0 += wq[(2 * j) * 128 + h * 32 + d] * kv;
            s1 += wq[(2 * j + 1) * 128 + h * 32 + d] * kv;
        }
        uint32_t hi, lo;
        split2h(s0 * invs, s1 * invs, hi, lo);
        *reinterpret_cast<uint2*>(g_Pil + n * 256 + 4 * j) = make_uint2(hi, lo);
    } else {                    // Wf^T [c2][n]
        int gg = g - 16384;
        int c2 = gg >> 7, j = gg & 127;
        int n0 = 2 * j, n1 = 2 * j + 1;
        int h = n0 >> 6;
        float s0 = 0.f, s1 = 0.f;
#pragma unroll
        for (int d = 0; d < 32; d++) {
            float ov = wo[(h * 32 + d) * 128 + c2];
            s0 += wv[(n0 & 63) * 128 + h * 32 + d] * ov;
            s1 += wv[(n1 & 63) * 128 + h * 32 + d] * ov;
        }
        uint32_t hi, lo;
        split2h(s0, s1, hi, lo);
        *reinterpret_cast<uint2*>(g_Wil + c2 * 512 + 4 * j) = make_uint2(hi, lo);
    }
}

// ---------------------------------------------------------------------------
__global__ void __launch_bounds__(512, 1)
attn_kernel(const float* __restrict__ tg, const float* __restrict__ z,
            const float* __restrict__ tmask, const float* __restrict__ bo,
            float* __restrict__ out) {
    extern __shared__ char sm[];
    const uint32_t smb = smem_u32(sm);
    float* s_bo   = reinterpret_cast<float*>(sm + OFF_BO);
    float* s_bias = reinterpret_cast<float*>(sm + OFF_BIAS);

    const int tid = threadIdx.x;
    const int lane = tid & 31, w = tid >> 5;
    const int c4 = lane & 3, lr = lane >> 2;
    const int mi = w >> 2;          // row band: pixels mi*16 .. +16
    const int hd = w & 3;           // head (G1) / c2-band (G2)
    const int P0 = blockIdx.x * 64;

    // ---- stage t (fp32 copy) via cp.async: 4 tt x 64 pix x 16 granules ----
#pragma unroll
    for (int it = 0; it < 8; it++) {
        int idx = tid + it * 512;
        int row = idx >> 4, i = idx & 15;     // row = tt*64+pix
        cp16(smb + OFF_T + (uint32_t)row * T_PITCH + i * 16,
             (const char*)tg +
                 (((size_t)(row >> 6) * NPIX + (size_t)(P0 + (row & 63))) * 64 + i * 4) * 4);
    }
    CP_COMMIT();
    // ---- stage B1 quarter 0 ----
#pragma unroll
    for (int it = 0; it < 4; it++) {
        int idx = tid + it * 512;
        int n = idx >> 3, i = idx & 7;
        cp16(smb + OFF_B + (uint32_t)n * B1_PITCH + i * 16,
             (const char*)g_Pil + n * 512 + i * 16);
    }
    CP_COMMIT();
    // ---- bo, bias, z split (manual) ----
    if (tid < 32) reinterpret_cast<float4*>(s_bo)[tid] =
        reinterpret_cast<const float4*>(bo)[tid];
    if (tid < 4) s_bias[tid] = INF_ * (tmask[tid] - 1.0f);
    {
        const float4* z4 = reinterpret_cast<const float4*>(z + (size_t)P0 * 128);
#pragma unroll
        for (int it = 0; it < 4; it++) {
            int e = tid + it * 512;
            float4 v = z4[e];
            int pix = e >> 5, q = e & 31;
            uint32_t h0, l0, h1, l1;
            split2h(v.x, v.y, h0, l0);
            split2h(v.z, v.w, h1, l1);
            *reinterpret_cast<uint4*>(sm + OFF_A + pix * A1_PITCH + q * 16) =
                make_uint4(h0, l0, h1, l1);
        }
    }

    // ---- GEMM1: 4 k-quarters, double-buffered B ----
    float acc1[8][4] = {};
#pragma unroll 1
    for (int q = 0; q < 4; q++) {
        CP_WAIT0();
        __syncthreads();
        if (q < 3) {            // prefetch next B1 quarter
#pragma unroll
            for (int it = 0; it < 4; it++) {
                int idx = tid + it * 512;
                int n = idx >> 3, i = idx & 7;
                cp16(smb + OFF_B + ((q + 1) & 1) * B_BUF + (uint32_t)n * B1_PITCH + i * 16,
                     (const char*)g_Pil + n * 512 + (q + 1) * 128 + i * 16);
            }
        } else {                // prefetch B2 quarter 0 into buf0
#pragma unroll
            for (int it = 0; it < 4; it++) {
                int idx = tid + it * 512;
                int c2 = idx >> 4, i = idx & 15;
                cp16(smb + OFF_B + (uint32_t)c2 * B2_PITCH + i * 16,
                     (const char*)g_Wil + c2 * 1024 + i * 16);
            }
        }
        CP_COMMIT();
#pragma unroll
        for (int kk = 0; kk < 2; kk++) {
            const int ks = q * 2 + kk;
            const char* ap = sm + OFF_A + (mi * 16 + lr) * A1_PITCH + 8 * (ks * 8 + c4);
            uint2 u00 = *reinterpret_cast<const uint2*>(ap);
            uint2 u01 = *reinterpret_cast<const uint2*>(ap + 32);
            uint2 u10 = *reinterpret_cast<const uint2*>(ap + 8 * A1_PITCH);
            uint2 u11 = *reinterpret_cast<const uint2*>(ap + 8 * A1_PITCH + 32);
#pragma unroll
            for (int np = 0; np < 8; np++) {
                const char* bp = sm + OFF_B + (q & 1) * B_BUF +
                                 (hd * 64 + np * 8 + lr) * B1_PITCH + 8 * (kk * 8 + c4);
                uint2 b0 = *reinterpret_cast<const uint2*>(bp);
                uint2 b1 = *reinterpret_cast<const uint2*>(bp + 32);
                mma16816(acc1[np], u00.x, u10.x, u01.x, u11.x, b0.x, b1.x);  // hi*hi
                mma16816(acc1[np], u00.x, u10.x, u01.x, u11.x, b0.y, b1.y);  // hi*lo
                mma16816(acc1[np], u00.y, u10.y, u01.y, u11.y, b0.x, b1.x);  // lo*hi
            }
        }
    }

    // ---- logits + softmax (fp32 t, in-lane over NT=4, quad reduce) ----
    float attn[2][4];
#pragma unroll
    for (int a = 0; a < 2; a++) {
        const int r = mi * 16 + 8 * a + lr;
        float lg0 = 0.f, lg1 = 0.f, lg2 = 0.f, lg3 = 0.f;
#pragma unroll
        for (int np = 0; np < 8; np++) {
            float d0 = acc1[np][2 * a], d1 = acc1[np][2 * a + 1];
            const char* tb = sm + OFF_T + r * T_PITCH + (np * 8 + 2 * c4) * 4;
            float2 f0 = *reinterpret_cast<const float2*>(tb);
            float2 f1 = *reinterpret_cast<const float2*>(tb + 64 * T_PITCH);
            float2 f2 = *reinterpret_cast<const float2*>(tb + 128 * T_PITCH);
            float2 f3 = *reinterpret_cast<const float2*>(tb + 192 * T_PITCH);
            lg0 += d0 * f0.x + d1 * f0.y;
            lg1 += d0 * f1.x + d1 * f1.y;
            lg2 += d0 * f2.x + d1 * f2.y;
            lg3 += d0 * f3.x + d1 * f3.y;
        }
        lg0 += __shfl_xor_sync(~0u, lg0, 1); lg0 += __shfl_xor_sync(~0u, lg0, 2);
        lg1 += __shfl_xor_sync(~0u, lg1, 1); lg1 += __shfl_xor_sync(~0u, lg1, 2);
        lg2 += __shfl_xor_sync(~0u, lg2, 1); lg2 += __shfl_xor_sync(~0u, lg2, 2);
        lg3 += __shfl_xor_sync(~0u, lg3, 1); lg3 += __shfl_xor_sync(~0u, lg3, 2);
        lg0 += s_bias[0]; lg1 += s_bias[1]; lg2 += s_bias[2]; lg3 += s_bias[3];
        float m = fmaxf(fmaxf(lg0, lg1), fmaxf(lg2, lg3));
        float e0 = __expf(lg0 - m), e1 = __expf(lg1 - m);
        float e2 = __expf(lg2 - m), e3 = __expf(lg3 - m);
        float inv = 1.f / (e0 + e1 + e2 + e3);
        attn[a][0] = e0 * inv; attn[a][1] = e1 * inv;
        attn[a][2] = e2 * inv; attn[a][3] = e3 * inv;
    }
    __syncthreads();   // A1 reads done everywhere before A2 overwrites region

    // ---- M2 build -> A2 (split fp16, interleaved) ----
#pragma unroll
    for (int a = 0; a < 2; a++) {
        const int r = mi * 16 + 8 * a + lr;
#pragma unroll
        for (int np = 0; np < 8; np++) {
            const char* tb = sm + OFF_T + r * T_PITCH + (np * 8 + 2 * c4) * 4;
            float2 f0 = *reinterpret_cast<const float2*>(tb);
            float2 f1 = *reinterpret_cast<const float2*>(tb + 64 * T_PITCH);
            float2 f2 = *reinterpret_cast<const float2*>(tb + 128 * T_PITCH);
            float2 f3 = *reinterpret_cast<const float2*>(tb + 192 * T_PITCH);
            float m0 = attn[a][0] * f0.x + attn[a][1] * f1.x +
                       attn[a][2] * f2.x + attn[a][3] * f3.x;
            float m1 = attn[a][0] * f0.y + attn[a][1] * f1.y +
                       attn[a][2] * f2.y + attn[a][3] * f3.y;
            uint32_t hi, lo;
            split2h(m0, m1, hi, lo);
            *reinterpret_cast<uint2*>(
                sm + OFF_A + r * A2_PITCH + 8 * (hd * 32 + np * 4 + c4)) =
                make_uint2(hi, lo);
        }
    }

    // ---- GEMM2: 4 k-quarters over K=256, double-buffered B2 ----
    float acc2[4][4] = {};
#pragma unroll 1
    for (int kq = 0; kq < 4; kq++) {
        CP_WAIT0();
        __syncthreads();         // kq==0: also publishes A2 everywhere
        if (kq < 3) {
#pragma unroll
            for (int it = 0; it < 4; it++) {
                int idx = tid + it * 512;
                int c2 = idx >> 4, i = idx & 15;
                cp16(smb + OFF_B + ((kq + 1) & 1) * B_BUF + (uint32_t)c2 * B2_PITCH + i * 16,
                     (const char*)g_Wil + c2 * 1024 + (kq + 1) * 256 + i * 16);
            }
            CP_COMMIT();
        }
#pragma unroll
        for (int kk = 0; kk < 4; kk++) {
            const int ks = kq * 4 + kk;
            const char* ap = sm + OFF_A + (mi * 16 + lr) * A2_PITCH + 8 * (ks * 8 + c4);
            uint2 u00 = *reinterpret_cast<const uint2*>(ap);
            uint2 u01 = *reinterpret_cast<const uint2*>(ap + 32);
            uint2 u10 = *reinterpret_cast<const uint2*>(ap + 8 * A2_PITCH);
            uint2 u11 = *reinterpret_cast<const uint2*>(ap + 8 * A2_PITCH + 32);
#pragma unroll
            for (int np = 0; np < 4; np++) {
                const char* bp = sm + OFF_B + (kq & 1) * B_BUF +
                                 (hd * 32 + np * 8 + lr) * B2_PITCH + 8 * (kk * 8 + c4);
                uint2 b0 = *reinterpret_cast<const uint2*>(bp);
                uint2 b1 = *reinterpret_cast<const uint2*>(bp + 32);
                mma16816(acc2[np], u00.x, u10.x, u01.x, u11.x, b0.x, b1.x);
                mma16816(acc2[np], u00.x, u10.x, u01.x, u11.x, b0.y, b1.y);
                mma16816(acc2[np], u00.y, u10.y, u01.y, u11.y, b0.x, b1.x);
            }
        }
    }

    // ---- output: add bias, STG.64 ----
#pragma unroll
    for (int a = 0; a < 2; a++) {
        const size_t r = (size_t)(P0 + mi * 16 + 8 * a + lr);
#pragma unroll
        for (int np = 0; np < 4; np++) {
            const int col = hd * 32 + np * 8 + 2 * c4;
            float2 b = *reinterpret_cast<const float2*>(s_bo + col);
            float2 v;
            v.x = acc2[np][2 * a] + b.x;
            v.y = acc2[np][2 * a + 1] + b.y;
            *reinterpret_cast<float2*>(out + r * 128 + col) = v;
        }
    }
}

// ---------------------------------------------------------------------------
extern "C" void kernel_launch(void* const* d_in, const int* in_sizes, int n_in,
                              void* d_out, int out_size) {
    const float* t     = (const float*)d_in[0];
    const float* z     = (const float*)d_in[1];
    const float* tmask = (const float*)d_in[2];
    const float* wq    = (const float*)d_in[3];
    const float* wk    = (const float*)d_in[4];
    const float* wv    = (const float*)d_in[5];
    const float* wo    = (const float*)d_in[6];
    const float* bo    = (const float*)d_in[7];
    float* out = (float*)d_out;

    cudaFuncSetAttribute(attn_kernel, cudaFuncAttributeMaxDynamicSharedMemorySize,
                         (int)SMEM_TOTAL);
    precompute_kernel<<<128, 256>>>(wq, wk, wv, wo);
    attn_kernel<<<NPIX / 64, 512, SMEM_TOTAL>>>(t, z, tmask, bo, out);
}

// round 8
// speedup vs baseline: 3.1714x; 1.4729x over previous
#include <cuda_runtime.h>
#include <cuda_fp16.h>
#include <cstdint>

// ---------------------------------------------------------------------------
// TemplatePointwiseAttention via mma.sync.m16n8k16, 2-pass fp16-split A,
// fp16 B (weights), ldmatrix.x4 fragment loads, cp.async double-buffered B.
//   GEMM1: L[64x256] = z[64x128] @ P ; logits/softmax -> attn -> M2
//   GEMM2: out[64x128] = M2[64x256] @ Wf + bo
// Warp (mi,hd): mi=w>>2 row band (16 pixels), hd=w&3 col band.
// ---------------------------------------------------------------------------

#define NPIX (512*512)
#define INF_ 100000.0f

// smem byte layout
#define OFF_BO   0u
#define OFF_BIAS 512u
#define OFF_A    1024u
#define A1_PITCH 272u        // 64 rows x 256B data; mod 128 = 16 (LDSM-clean)
#define A1_PLANE 17408u      // lo plane offset
#define A2_PITCH 528u        // 64 rows x 512B data; mod 128 = 16
#define A2_PLANE 33792u
#define OFF_B    68608u      // two buffers
#define B_BUF    36864u
#define B1_PITCH 144u        // 256 rows x 128B data; mod 128 = 16
#define B2_PITCH 272u        // 128 rows x 256B data; mod 128 = 16
#define OFF_T    142336u
#define T_PITCH  288u        // 256 rows x 256B fp32
#define SMEM_TOTAL 216064u

__device__ __align__(16) __half g_Phi[256 * 128];  // [n][c]   fp16
__device__ __align__(16) __half g_Whi[128 * 256];  // [c2][n]  fp16

__device__ __forceinline__ uint32_t smem_u32(const void* p) {
    uint32_t a;
    asm("{ .reg .u64 t; cvta.to.shared.u64 t, %1; cvt.u32.u64 %0, t; }" : "=r"(a) : "l"(p));
    return a;
}
__device__ __forceinline__ void mma16816(float* d, uint32_t a0, uint32_t a1,
                                         uint32_t a2, uint32_t a3,
                                         uint32_t b0, uint32_t b1) {
    asm volatile(
        "mma.sync.aligned.m16n8k16.row.col.f32.f16.f16.f32 "
        "{%0,%1,%2,%3}, {%4,%5,%6,%7}, {%8,%9}, {%0,%1,%2,%3};"
        : "+f"(d[0]), "+f"(d[1]), "+f"(d[2]), "+f"(d[3])
        : "r"(a0), "r"(a1), "r"(a2), "r"(a3), "r"(b0), "r"(b1));
}
#define LDSM4(R0, R1, R2, R3, ADDR) \
    asm volatile("ldmatrix.sync.aligned.m8n8.x4.shared.b16 {%0,%1,%2,%3}, [%4];" \
        : "=r"(R0), "=r"(R1), "=r"(R2), "=r"(R3) : "r"(ADDR))
__device__ __forceinline__ void cp16(uint32_t dst, const void* src) {
    asm volatile("cp.async.cg.shared.global [%0], [%1], 16;" :: "r"(dst), "l"(src));
}
#define CP_COMMIT() asm volatile("cp.async.commit_group;" ::: "memory")
#define CP_WAIT0()  asm volatile("cp.async.wait_group 0;" ::: "memory")

// ---------------------------------------------------------------------------
__global__ void precompute_kernel(const float* __restrict__ wq,
                                  const float* __restrict__ wk,
                                  const float* __restrict__ wv,
                                  const float* __restrict__ wo) {
    int g = blockIdx.x * blockDim.x + threadIdx.x;   // 0..65535
    const float invs = 0.17677669529663689f;         // 1/sqrt(32)
    if (g < 32768) {            // P^T [n][c]
        int n = g >> 7, c = g & 127;
        int h = n >> 6, ct = n & 63;
        float s = 0.f;
#pragma unroll
        for (int d = 0; d < 32; d++)
            s += wq[c * 128 + h * 32 + d] * wk[ct * 128 + h * 32 + d];
        g_Phi[n * 128 + c] = __float2half_rn(s * invs);
    } else {                    // Wf^T [c2][n]
        int gg = g - 32768;
        int c2 = gg >> 8, n = gg & 255;
        int h = n >> 6, ct = n & 63;
        float s = 0.f;
#pragma unroll
        for (int d = 0; d < 32; d++)
            s += wv[ct * 128 + h * 32 + d] * wo[(h * 32 + d) * 128 + c2];
        g_Whi[c2 * 256 + n] = __float2half_rn(s);
    }
}

// ---------------------------------------------------------------------------
__global__ void __launch_bounds__(512, 1)
attn_kernel(const float* __restrict__ tg, const float* __restrict__ z,
            const float* __restrict__ tmask, const float* __restrict__ bo,
            float* __restrict__ out) {
    extern __shared__ char sm[];
    const uint32_t smb = smem_u32(sm);
    float* s_bo   = reinterpret_cast<float*>(sm + OFF_BO);
    float* s_bias = reinterpret_cast<float*>(sm + OFF_BIAS);

    const int tid = threadIdx.x;
    const int lane = tid & 31, w = tid >> 5;
    const int c4 = lane & 3, lr = lane >> 2;
    const int mi = w >> 2;          // row band: pixels mi*16 .. +16
    const int hd = w & 3;           // head (G1) / c2-band (G2)
    const int P0 = blockIdx.x * 64;

    // ---- stage t (fp32) via cp.async ----
#pragma unroll
    for (int it = 0; it < 8; it++) {
        int idx = tid + it * 512;
        int row = idx >> 4, i = idx & 15;     // row = tt*64+pix
        cp16(smb + OFF_T + (uint32_t)row * T_PITCH + i * 16,
             (const char*)tg +
                 (((size_t)(row >> 6) * NPIX + (size_t)(P0 + (row & 63))) * 64 + i * 4) * 4);
    }
    CP_COMMIT();
    // ---- stage B1 chunk 0 (k 0..63) ----
#pragma unroll
    for (int it = 0; it < 4; it++) {
        int idx = tid + it * 512;
        int n = idx >> 3, i = idx & 7;
        cp16(smb + OFF_B + (uint32_t)n * B1_PITCH + i * 16,
             (const char*)(g_Phi + n * 128 + i * 8));
    }
    CP_COMMIT();
    // ---- bo, bias, z split (manual) ----
    if (tid < 32) reinterpret_cast<float4*>(s_bo)[tid] =
        reinterpret_cast<const float4*>(bo)[tid];
    if (tid < 4) s_bias[tid] = INF_ * (tmask[tid] - 1.0f);
    {
        const float4* z4 = reinterpret_cast<const float4*>(z + (size_t)P0 * 128);
#pragma unroll
        for (int it = 0; it < 4; it++) {
            int e = tid + it * 512;
            float4 v = z4[e];
            int pix = e >> 5, q = e & 31;
            __half2 h0 = __floats2half2_rn(v.x, v.y);
            __half2 h1 = __floats2half2_rn(v.z, v.w);
            float2 f0 = __half22float2(h0), f1 = __half22float2(h1);
            __half2 l0 = __floats2half2_rn(v.x - f0.x, v.y - f0.y);
            __half2 l1 = __floats2half2_rn(v.z - f1.x, v.w - f1.y);
            char* dst = sm + OFF_A + pix * A1_PITCH + 8 * q;
            *reinterpret_cast<uint2*>(dst) =
                make_uint2(*reinterpret_cast<uint32_t*>(&h0), *reinterpret_cast<uint32_t*>(&h1));
            *reinterpret_cast<uint2*>(dst + A1_PLANE) =
                make_uint2(*reinterpret_cast<uint32_t*>(&l0), *reinterpret_cast<uint32_t*>(&l1));
        }
    }

    // ---- fragment base addresses ----
    const uint32_t bRow  = ((lane >> 4) << 3) + (lane & 7);   // ldmatrix B row-in-16
    const uint32_t bKoff = ((lane >> 3) & 1) << 4;
    const uint32_t aAhi = smb + OFF_A + (mi * 16 + (lane & 15)) * A1_PITCH + (lane >> 4) * 16;
    const uint32_t aAlo = aAhi + A1_PLANE;
    const uint32_t aB1  = smb + OFF_B + (hd * 64 + bRow) * B1_PITCH + bKoff;

    // ---- GEMM1: 2 k-chunks (64 each), double-buffered B ----
    float acc1[8][4] = {};
#pragma unroll 1
    for (int c = 0; c < 2; c++) {
        CP_WAIT0();
        __syncthreads();
        if (c == 0) {            // prefetch B1 chunk1
#pragma unroll
            for (int it = 0; it < 4; it++) {
                int idx = tid + it * 512;
                int n = idx >> 3, i = idx & 7;
                cp16(smb + OFF_B + B_BUF + (uint32_t)n * B1_PITCH + i * 16,
                     (const char*)(g_Phi + n * 128 + 64 + i * 8));
            }
        } else {                 // prefetch B2 chunk0 into buf0
#pragma unroll
            for (int it = 0; it < 4; it++) {
                int idx = tid + it * 512;
                int c2 = idx >> 4, i = idx & 15;
                cp16(smb + OFF_B + (uint32_t)c2 * B2_PITCH + i * 16,
                     (const char*)(g_Whi + c2 * 256 + i * 8));
            }
        }
        CP_COMMIT();
#pragma unroll
        for (int kk = 0; kk < 4; kk++) {
            const uint32_t ka = c * 128 + kk * 32;
            uint32_t r0, r1, r2, r3, s0, s1, s2, s3;
            LDSM4(r0, r1, r2, r3, aAhi + ka);
            LDSM4(s0, s1, s2, s3, aAlo + ka);
#pragma unroll
            for (int g = 0; g < 4; g++) {
                uint32_t b0, b1, b2, b3;
                LDSM4(b0, b1, b2, b3, aB1 + c * B_BUF + g * (16 * B1_PITCH) + kk * 32);
                mma16816(acc1[2 * g],     r0, r1, r2, r3, b0, b1);
                mma16816(acc1[2 * g],     s0, s1, s2, s3, b0, b1);
                mma16816(acc1[2 * g + 1], r0, r1, r2, r3, b2, b3);
                mma16816(acc1[2 * g + 1], s0, s1, s2, s3, b2, b3);
            }
        }
    }

    // ---- logits + softmax (fp32 t, in-lane over NT=4, quad reduce) ----
    float attn[2][4];
#pragma unroll
    for (int a = 0; a < 2; a++) {
        const int r = mi * 16 + 8 * a + lr;
        float lg0 = 0.f, lg1 = 0.f, lg2 = 0.f, lg3 = 0.f;
#pragma unroll
        for (int np = 0; np < 8; np++) {
            float d0 = acc1[np][2 * a], d1 = acc1[np][2 * a + 1];
            const char* tb = sm + OFF_T + r * T_PITCH + (np * 8 + 2 * c4) * 4;
            float2 f0 = *reinterpret_cast<const float2*>(tb);
            float2 f1 = *reinterpret_cast<const float2*>(tb + 64 * T_PITCH);
            float2 f2 = *reinterpret_cast<const float2*>(tb + 128 * T_PITCH);
            float2 f3 = *reinterpret_cast<const float2*>(tb + 192 * T_PITCH);
            lg0 += d0 * f0.x + d1 * f0.y;
            lg1 += d0 * f1.x + d1 * f1.y;
            lg2 += d0 * f2.x + d1 * f2.y;
            lg3 += d0 * f3.x + d1 * f3.y;
        }
        lg0 += __shfl_xor_sync(~0u, lg0, 1); lg0 += __shfl_xor_sync(~0u, lg0, 2);
        lg1 += __shfl_xor_sync(~0u, lg1, 1); lg1 += __shfl_xor_sync(~0u, lg1, 2);
        lg2 += __shfl_xor_sync(~0u, lg2, 1); lg2 += __shfl_xor_sync(~0u, lg2, 2);
        lg3 += __shfl_xor_sync(~0u, lg3, 1); lg3 += __shfl_xor_sync(~0u, lg3, 2);
        lg0 += s_bias[0]; lg1 += s_bias[1]; lg2 += s_bias[2]; lg3 += s_bias[3];
        float m = fmaxf(fmaxf(lg0, lg1), fmaxf(lg2, lg3));
        float e0 = __expf(lg0 - m), e1 = __expf(lg1 - m);
        float e2 = __expf(lg2 - m), e3 = __expf(lg3 - m);
        float inv = 1.f / (e0 + e1 + e2 + e3);
        attn[a][0] = e0 * inv; attn[a][1] = e1 * inv;
        attn[a][2] = e2 * inv; attn[a][3] = e3 * inv;
    }
    __syncthreads();   // all A1 fragment reads done before A2 overwrites region

    // ---- M2 build -> A2 (split fp16, separate hi/lo planes) ----
#pragma unroll
    for (int a = 0; a < 2; a++) {
        const int r = mi * 16 + 8 * a + lr;
#pragma unroll
        for (int np = 0; np < 8; np++) {
            const char* tb = sm + OFF_T + r * T_PITCH + (np * 8 + 2 * c4) * 4;
            float2 f0 = *reinterpret_cast<const float2*>(tb);
            float2 f1 = *reinterpret_cast<const float2*>(tb + 64 * T_PITCH);
            float2 f2 = *reinterpret_cast<const float2*>(tb + 128 * T_PITCH);
            float2 f3 = *reinterpret_cast<const float2*>(tb + 192 * T_PITCH);
            float m0 = attn[a][0] * f0.x + attn[a][1] * f1.x +
                       attn[a][2] * f2.x + attn[a][3] * f3.x;
            float m1 = attn[a][0] * f0.y + attn[a][1] * f1.y +
                       attn[a][2] * f2.y + attn[a][3] * f3.y;
            __half2 h = __floats2half2_rn(m0, m1);
            float2 hf = __half22float2(h);
            __half2 l = __floats2half2_rn(m0 - hf.x, m1 - hf.y);
            char* dst = sm + OFF_A + r * A2_PITCH + (hd * 64 + np * 8 + 2 * c4) * 2;
            *reinterpret_cast<uint32_t*>(dst) = *reinterpret_cast<uint32_t*>(&h);
            *reinterpret_cast<uint32_t*>(dst + A2_PLANE) = *reinterpret_cast<uint32_t*>(&l);
        }
    }

    // ---- GEMM2: 2 k-chunks (128 each), double-buffered B2 ----
    const uint32_t aA2hi = smb + OFF_A + (mi * 16 + (lane & 15)) * A2_PITCH + (lane >> 4) * 16;
    const uint32_t aA2lo = aA2hi + A2_PLANE;
    const uint32_t aB2   = smb + OFF_B + (hd * 32 + bRow) * B2_PITCH + bKoff;
    float acc2[4][4] = {};
#pragma unroll 1
    for (int c = 0; c < 2; c++) {
        CP_WAIT0();
        __syncthreads();         // c==0: also publishes A2 everywhere
        if (c == 0) {
#pragma unroll
            for (int it = 0; it < 4; it++) {
                int idx = tid + it * 512;
                int c2 = idx >> 4, i = idx & 15;
                cp16(smb + OFF_B + B_BUF + (uint32_t)c2 * B2_PITCH + i * 16,
                     (const char*)(g_Whi + c2 * 256 + 128 + i * 8));
            }
            CP_COMMIT();
        }
#pragma unroll
        for (int kk = 0; kk < 8; kk++) {
            const uint32_t ka = c * 256 + kk * 32;
            uint32_t r0, r1, r2, r3, s0, s1, s2, s3;
            LDSM4(r0, r1, r2, r3, aA2hi + ka);
            LDSM4(s0, s1, s2, s3, aA2lo + ka);
#pragma unroll
            for (int g = 0; g < 2; g++) {
                uint32_t b0, b1, b2, b3;
                LDSM4(b0, b1, b2, b3, aB2 + c * B_BUF + g * (16 * B2_PITCH) + kk * 32);
                mma16816(acc2[2 * g],     r0, r1, r2, r3, b0, b1);
                mma16816(acc2[2 * g],     s0, s1, s2, s3, b0, b1);
                mma16816(acc2[2 * g + 1], r0, r1, r2, r3, b2, b3);
                mma16816(acc2[2 * g + 1], s0, s1, s2, s3, b2, b3);
            }
        }
    }

    // ---- output: add bias, STG.64 ----
#pragma unroll
    for (int a = 0; a < 2; a++) {
        const size_t r = (size_t)(P0 + mi * 16 + 8 * a + lr);
#pragma unroll
        for (int np = 0; np < 4; np++) {
            const int col = hd * 32 + np * 8 + 2 * c4;
            float2 b = *reinterpret_cast<const float2*>(s_bo + col);
            float2 v;
            v.x = acc2[np][2 * a] + b.x;
            v.y = acc2[np][2 * a + 1] + b.y;
            *reinterpret_cast<float2*>(out + r * 128 + col) = v;
        }
    }
}

// ---------------------------------------------------------------------------
extern "C" void kernel_launch(void* const* d_in, const int* in_sizes, int n_in,
                              void* d_out, int out_size) {
    const float* t     = (const float*)d_in[0];
    const float* z     = (const float*)d_in[1];
    const float* tmask = (const float*)d_in[2];
    const float* wq    = (const float*)d_in[3];
    const float* wk    = (const float*)d_in[4];
    const float* wv    = (const float*)d_in[5];
    const float* wo    = (const float*)d_in[6];
    const float* bo    = (const float*)d_in[7];
    float* out = (float*)d_out;

    cudaFuncSetAttribute(attn_kernel, cudaFuncAttributeMaxDynamicSharedMemorySize,
                         (int)SMEM_TOTAL);
    precompute_kernel<<<256, 256>>>(wq, wk, wv, wo);
    attn_kernel<<<NPIX / 64, 512, SMEM_TOTAL>>>(t, z, tmask, bo, out);
}

// round 9
// speedup vs baseline: 3.8510x; 1.2143x over previous
#include <cuda_runtime.h>
#include <cuda_fp16.h>
#include <cstdint>

// ---------------------------------------------------------------------------
// TemplatePointwiseAttention via mma.sync.m16n8k16, all-fp16 operands
// (fp32 accum), ldmatrix.x4 fragment loads, cp.async double-buffered B.
//   GEMM1: L[64x256] = z[64x128] @ P ; logits/softmax -> attn -> M2
//   GEMM2: out[64x128] = M2[64x256] @ Wf + bo
// Warp (mi,hd): mi=w>>2 row band (16 pixels), hd=w&3 col band (head / c2).
// R9: single-pass fp16 (no lo-residual passes), fp16 t in smem (pitch 144),
//     conflict-free epilogue banking.
// ---------------------------------------------------------------------------

#define NPIX (512*512)
#define INF_ 100000.0f

// smem byte layout
#define OFF_BO   0u
#define OFF_BIAS 512u
#define OFF_A    1024u
#define A1_PITCH 272u        // 64 rows x 256B fp16 z; mod128=16 (LDSM-clean)
#define A2_PITCH 528u        // 64 rows x 512B fp16 M2; mod128=16
#define OFF_B    34816u      // two buffers
#define B_BUF    36864u
#define B1_PITCH 144u        // 256 rows x 128B; mod128=16
#define B2_PITCH 272u        // 128 rows x 256B; mod128=16
#define OFF_T    108544u
#define T_PITCH  144u        // 256 rows x 128B fp16 t; 36 words ≡ 4 mod 32
#define SMEM_TOTAL 145408u

__device__ __align__(16) __half g_Phi[256 * 128];  // [n][c]   fp16
__device__ __align__(16) __half g_Whi[128 * 256];  // [c2][n]  fp16

__device__ __forceinline__ uint32_t smem_u32(const void* p) {
    uint32_t a;
    asm("{ .reg .u64 t; cvta.to.shared.u64 t, %1; cvt.u32.u64 %0, t; }" : "=r"(a) : "l"(p));
    return a;
}
__device__ __forceinline__ void mma16816(float* d, uint32_t a0, uint32_t a1,
                                         uint32_t a2, uint32_t a3,
                                         uint32_t b0, uint32_t b1) {
    asm volatile(
        "mma.sync.aligned.m16n8k16.row.col.f32.f16.f16.f32 "
        "{%0,%1,%2,%3}, {%4,%5,%6,%7}, {%8,%9}, {%0,%1,%2,%3};"
        : "+f"(d[0]), "+f"(d[1]), "+f"(d[2]), "+f"(d[3])
        : "r"(a0), "r"(a1), "r"(a2), "r"(a3), "r"(b0), "r"(b1));
}
#define LDSM4(R0, R1, R2, R3, ADDR) \
    asm volatile("ldmatrix.sync.aligned.m8n8.x4.shared.b16 {%0,%1,%2,%3}, [%4];" \
        : "=r"(R0), "=r"(R1), "=r"(R2), "=r"(R3) : "r"(ADDR))
__device__ __forceinline__ void cp16(uint32_t dst, const void* src) {
    asm volatile("cp.async.cg.shared.global [%0], [%1], 16;" :: "r"(dst), "l"(src));
}
#define CP_COMMIT() asm volatile("cp.async.commit_group;" ::: "memory")
#define CP_WAIT0()  asm volatile("cp.async.wait_group 0;" ::: "memory")

// ---------------------------------------------------------------------------
__global__ void precompute_kernel(const float* __restrict__ wq,
                                  const float* __restrict__ wk,
                                  const float* __restrict__ wv,
                                  const float* __restrict__ wo) {
    int g = blockIdx.x * blockDim.x + threadIdx.x;   // 0..65535
    const float invs = 0.17677669529663689f;         // 1/sqrt(32)
    if (g < 32768) {            // P^T [n][c]
        int n = g >> 7, c = g & 127;
        int h = n >> 6, ct = n & 63;
        float s = 0.f;
#pragma unroll
        for (int d = 0; d < 32; d++)
            s += wq[c * 128 + h * 32 + d] * wk[ct * 128 + h * 32 + d];
        g_Phi[n * 128 + c] = __float2half_rn(s * invs);
    } else {                    // Wf^T [c2][n]
        int gg = g - 32768;
        int c2 = gg >> 8, n = gg & 255;
        int h = n >> 6, ct = n & 63;
        float s = 0.f;
#pragma unroll
        for (int d = 0; d < 32; d++)
            s += wv[ct * 128 + h * 32 + d] * wo[(h * 32 + d) * 128 + c2];
        g_Whi[c2 * 256 + n] = __float2half_rn(s);
    }
}

// ---------------------------------------------------------------------------
__global__ void __launch_bounds__(512, 1)
attn_kernel(const float* __restrict__ tg, const float* __restrict__ z,
            const float* __restrict__ tmask, const float* __restrict__ bo,
            float* __restrict__ out) {
    extern __shared__ char sm[];
    const uint32_t smb = smem_u32(sm);
    float* s_bo   = reinterpret_cast<float*>(sm + OFF_BO);
    float* s_bias = reinterpret_cast<float*>(sm + OFF_BIAS);

    const int tid = threadIdx.x;
    const int lane = tid & 31, w = tid >> 5;
    const int c4 = lane & 3, lr = lane >> 2;
    const int mi = w >> 2;          // row band: pixels mi*16 .. +16
    const int hd = w & 3;           // head (G1) / c2-band (G2)
    const int P0 = blockIdx.x * 64;

    // ---- stage B1 chunk 0 (k 0..63) via cp.async ----
#pragma unroll
    for (int it = 0; it < 4; it++) {
        int idx = tid + it * 512;
        int n = idx >> 3, i = idx & 7;
        cp16(smb + OFF_B + (uint32_t)n * B1_PITCH + i * 16,
             (const char*)(g_Phi + n * 128 + i * 8));
    }
    CP_COMMIT();

    // ---- bo, bias ----
    if (tid < 32) reinterpret_cast<float4*>(s_bo)[tid] =
        reinterpret_cast<const float4*>(bo)[tid];
    if (tid < 4) s_bias[tid] = INF_ * (tmask[tid] - 1.0f);

    // ---- stage z -> A1 fp16 ----
    {
        const float4* z4 = reinterpret_cast<const float4*>(z + (size_t)P0 * 128);
#pragma unroll
        for (int it = 0; it < 4; it++) {
            int e = tid + it * 512;
            float4 v = z4[e];
            int pix = e >> 5, q = e & 31;
            __half2 h0 = __floats2half2_rn(v.x, v.y);
            __half2 h1 = __floats2half2_rn(v.z, v.w);
            *reinterpret_cast<uint2*>(sm + OFF_A + pix * A1_PITCH + 8 * q) =
                make_uint2(*reinterpret_cast<uint32_t*>(&h0),
                           *reinterpret_cast<uint32_t*>(&h1));
        }
    }
    // ---- stage t -> fp16 smem (row = tt*64+pix, 128B data, pitch 144) ----
    {
        const float4* t4 = reinterpret_cast<const float4*>(tg);
#pragma unroll
        for (int it = 0; it < 8; it++) {
            int e = tid + it * 512;
            int row = e >> 4, i = e & 15;
            float4 v = t4[((size_t)(row >> 6) * NPIX + (size_t)(P0 + (row & 63))) * 16 + i];
            __half2 h0 = __floats2half2_rn(v.x, v.y);
            __half2 h1 = __floats2half2_rn(v.z, v.w);
            *reinterpret_cast<uint2*>(sm + OFF_T + row * T_PITCH + i * 8) =
                make_uint2(*reinterpret_cast<uint32_t*>(&h0),
                           *reinterpret_cast<uint32_t*>(&h1));
        }
    }

    // ---- fragment base addresses ----
    const uint32_t bRow  = ((lane >> 4) << 3) + (lane & 7);
    const uint32_t bKoff = ((lane >> 3) & 1) << 4;
    const uint32_t aA1 = smb + OFF_A + (mi * 16 + (lane & 15)) * A1_PITCH + (lane >> 4) * 16;
    const uint32_t aB1 = smb + OFF_B + (hd * 64 + bRow) * B1_PITCH + bKoff;

    // ---- GEMM1: 2 k-chunks (64 each), double-buffered B ----
    float acc1[8][4] = {};
#pragma unroll 1
    for (int c = 0; c < 2; c++) {
        CP_WAIT0();
        __syncthreads();
        if (c == 0) {            // prefetch B1 chunk1
#pragma unroll
            for (int it = 0; it < 4; it++) {
                int idx = tid + it * 512;
                int n = idx >> 3, i = idx & 7;
                cp16(smb + OFF_B + B_BUF + (uint32_t)n * B1_PITCH + i * 16,
                     (const char*)(g_Phi + n * 128 + 64 + i * 8));
            }
        } else {                 // prefetch B2 chunk0 into buf0
#pragma unroll
            for (int it = 0; it < 4; it++) {
                int idx = tid + it * 512;
                int c2 = idx >> 4, i = idx & 15;
                cp16(smb + OFF_B + (uint32_t)c2 * B2_PITCH + i * 16,
                     (const char*)(g_Whi + c2 * 256 + i * 8));
            }
        }
        CP_COMMIT();
#pragma unroll
        for (int kk = 0; kk < 4; kk++) {
            const uint32_t ka = c * 128 + kk * 32;
            uint32_t r0, r1, r2, r3;
            LDSM4(r0, r1, r2, r3, aA1 + ka);
#pragma unroll
            for (int g = 0; g < 4; g++) {
                uint32_t b0, b1, b2, b3;
                LDSM4(b0, b1, b2, b3, aB1 + c * B_BUF + g * (16 * B1_PITCH) + kk * 32);
                mma16816(acc1[2 * g],     r0, r1, r2, r3, b0, b1);
                mma16816(acc1[2 * g + 1], r0, r1, r2, r3, b2, b3);
            }
        }
    }

    // ---- logits + softmax (fp16 t, in-lane over NT=4, quad reduce) ----
    float attn[2][4];
#pragma unroll
    for (int a = 0; a < 2; a++) {
        const int r = mi * 16 + 8 * a + lr;
        float lg0 = 0.f, lg1 = 0.f, lg2 = 0.f, lg3 = 0.f;
#pragma unroll
        for (int np = 0; np < 8; np++) {
            float d0 = acc1[np][2 * a], d1 = acc1[np][2 * a + 1];
            const char* tb = sm + OFF_T + r * T_PITCH + (np * 8 + 2 * c4) * 2;
            float2 f0 = __half22float2(*reinterpret_cast<const __half2*>(tb));
            float2 f1 = __half22float2(*reinterpret_cast<const __half2*>(tb + 64 * T_PITCH));
            float2 f2 = __half22float2(*reinterpret_cast<const __half2*>(tb + 128 * T_PITCH));
            float2 f3 = __half22float2(*reinterpret_cast<const __half2*>(tb + 192 * T_PITCH));
            lg0 += d0 * f0.x + d1 * f0.y;
            lg1 += d0 * f1.x + d1 * f1.y;
            lg2 += d0 * f2.x + d1 * f2.y;
            lg3 += d0 * f3.x + d1 * f3.y;
        }
        lg0 += __shfl_xor_sync(~0u, lg0, 1); lg0 += __shfl_xor_sync(~0u, lg0, 2);
        lg1 += __shfl_xor_sync(~0u, lg1, 1); lg1 += __shfl_xor_sync(~0u, lg1, 2);
        lg2 += __shfl_xor_sync(~0u, lg2, 1); lg2 += __shfl_xor_sync(~0u, lg2, 2);
        lg3 += __shfl_xor_sync(~0u, lg3, 1); lg3 += __shfl_xor_sync(~0u, lg3, 2);
        lg0 += s_bias[0]; lg1 += s_bias[1]; lg2 += s_bias[2]; lg3 += s_bias[3];
        float m = fmaxf(fmaxf(lg0, lg1), fmaxf(lg2, lg3));
        float e0 = __expf(lg0 - m), e1 = __expf(lg1 - m);
        float e2 = __expf(lg2 - m), e3 = __expf(lg3 - m);
        float inv = 1.f / (e0 + e1 + e2 + e3);
        attn[a][0] = e0 * inv; attn[a][1] = e1 * inv;
        attn[a][2] = e2 * inv; attn[a][3] = e3 * inv;
    }
    __syncthreads();   // all A1 fragment reads done before A2 overwrites region

    // ---- M2 build -> A2 (fp16); STS.32 banks 4*lr+c4: conflict-free ----
#pragma unroll
    for (int a = 0; a < 2; a++) {
        const int r = mi * 16 + 8 * a + lr;
#pragma unroll
        for (int np = 0; np < 8; np++) {
            const char* tb = sm + OFF_T + r * T_PITCH + (np * 8 + 2 * c4) * 2;
            float2 f0 = __half22float2(*reinterpret_cast<const __half2*>(tb));
            float2 f1 = __half22float2(*reinterpret_cast<const __half2*>(tb + 64 * T_PITCH));
            float2 f2 = __half22float2(*reinterpret_cast<const __half2*>(tb + 128 * T_PITCH));
            float2 f3 = __half22float2(*reinterpret_cast<const __half2*>(tb + 192 * T_PITCH));
            float m0 = attn[a][0] * f0.x + attn[a][1] * f1.x +
                       attn[a][2] * f2.x + attn[a][3] * f3.x;
            float m1 = attn[a][0] * f0.y + attn[a][1] * f1.y +
                       attn[a][2] * f2.y + attn[a][3] * f3.y;
            __half2 h = __floats2half2_rn(m0, m1);
            *reinterpret_cast<uint32_t*>(
                sm + OFF_A + r * A2_PITCH + (hd * 64 + np * 8 + 2 * c4) * 2) =
                *reinterpret_cast<uint32_t*>(&h);
        }
    }

    // ---- GEMM2: 2 k-chunks (128 each), double-buffered B2 ----
    const uint32_t aA2 = smb + OFF_A + (mi * 16 + (lane & 15)) * A2_PITCH + (lane >> 4) * 16;
    const uint32_t aB2 = smb + OFF_B + (hd * 32 + bRow) * B2_PITCH + bKoff;
    float acc2[4][4] = {};
#pragma unroll 1
    for (int c = 0; c < 2; c++) {
        CP_WAIT0();
        __syncthreads();         // c==0: also publishes A2 everywhere
        if (c == 0) {
#pragma unroll
            for (int it = 0; it < 4; it++) {
                int idx = tid + it * 512;
                int c2 = idx >> 4, i = idx & 15;
                cp16(smb + OFF_B + B_BUF + (uint32_t)c2 * B2_PITCH + i * 16,
                     (const char*)(g_Whi + c2 * 256 + 128 + i * 8));
            }
            CP_COMMIT();
        }
#pragma unroll
        for (int kk = 0; kk < 8; kk++) {
            const uint32_t ka = c * 256 + kk * 32;
            uint32_t r0, r1, r2, r3;
            LDSM4(r0, r1, r2, r3, aA2 + ka);
#pragma unroll
            for (int g = 0; g < 2; g++) {
                uint32_t b0, b1, b2, b3;
                LDSM4(b0, b1, b2, b3, aB2 + c * B_BUF + g * (16 * B2_PITCH) + kk * 32);
                mma16816(acc2[2 * g],     r0, r1, r2, r3, b0, b1);
                mma16816(acc2[2 * g + 1], r0, r1, r2, r3, b2, b3);
            }
        }
    }

    // ---- output: add bias, STG.64 ----
#pragma unroll
    for (int a = 0; a < 2; a++) {
        const size_t r = (size_t)(P0 + mi * 16 + 8 * a + lr);
#pragma unroll
        for (int np = 0; np < 4; np++) {
            const int col = hd * 32 + np * 8 + 2 * c4;
            float2 b = *reinterpret_cast<const float2*>(s_bo + col);
            float2 v;
            v.x = acc2[np][2 * a] + b.x;
            v.y = acc2[np][2 * a + 1] + b.y;
            *reinterpret_cast<float2*>(out + r * 128 + col) = v;
        }
    }
}

// ---------------------------------------------------------------------------
extern "C" void kernel_launch(void* const* d_in, const int* in_sizes, int n_in,
                              void* d_out, int out_size) {
    const float* t     = (const float*)d_in[0];
    const float* z     = (const float*)d_in[1];
    const float* tmask = (const float*)d_in[2];
    const float* wq    = (const float*)d_in[3];
    const float* wk    = (const float*)d_in[4];
    const float* wv    = (const float*)d_in[5];
    const float* wo    = (const float*)d_in[6];
    const float* bo    = (const float*)d_in[7];
    float* out = (float*)d_out;

    cudaFuncSetAttribute(attn_kernel, cudaFuncAttributeMaxDynamicSharedMemorySize,
                         (int)SMEM_TOTAL);
    precompute_kernel<<<256, 256>>>(wq, wk, wv, wo);
    attn_kernel<<<NPIX / 64, 512, SMEM_TOTAL>>>(t, z, tmask, bo, out);
}

// round 10
// speedup vs baseline: 4.0736x; 1.0578x over previous
#include <cuda_runtime.h>
#include <cuda_fp16.h>
#include <cstdint>

// ---------------------------------------------------------------------------
// TemplatePointwiseAttention via mma.sync.m16n8k16, all-fp16 operands
// (fp32 accum), ldmatrix.x4, cp.async double-buffered B.
// R10: 256 threads / 8 warps, warp tiles G1 32x64 / G2 32x32 (B-frag reuse
//      across 2 m16 frags), register-cached t epilogue (single t read).
// Warp (mi,hd): mi=w>>2 in {0,1} (32-pixel band), hd=w&3 (head / c2 band).
// ---------------------------------------------------------------------------

#define NPIX (512*512)
#define INF_ 100000.0f

// smem byte layout (same footprint as R9)
#define OFF_BO   0u
#define OFF_BIAS 512u
#define OFF_A    1024u
#define A1_PITCH 272u        // 64 rows x 256B fp16 z; mod128=16 (LDSM-clean)
#define A2_PITCH 528u        // 64 rows x 512B fp16 M2; mod128=16
#define OFF_B    34816u      // two buffers
#define B_BUF    36864u
#define B1_PITCH 144u        // 256 rows x 128B; mod128=16
#define B2_PITCH 272u        // 128 rows x 256B; mod128=16
#define OFF_T    108544u
#define T_PITCH  144u        // 256 rows x 128B fp16 t; 36 words == 4 mod 32
#define SMEM_TOTAL 145408u

__device__ __align__(16) __half g_Phi[256 * 128];  // [n][c]   fp16
__device__ __align__(16) __half g_Whi[128 * 256];  // [c2][n]  fp16

__device__ __forceinline__ uint32_t smem_u32(const void* p) {
    uint32_t a;
    asm("{ .reg .u64 t; cvta.to.shared.u64 t, %1; cvt.u32.u64 %0, t; }" : "=r"(a) : "l"(p));
    return a;
}
__device__ __forceinline__ void mma16816(float* d, uint32_t a0, uint32_t a1,
                                         uint32_t a2, uint32_t a3,
                                         uint32_t b0, uint32_t b1) {
    asm volatile(
        "mma.sync.aligned.m16n8k16.row.col.f32.f16.f16.f32 "
        "{%0,%1,%2,%3}, {%4,%5,%6,%7}, {%8,%9}, {%0,%1,%2,%3};"
        : "+f"(d[0]), "+f"(d[1]), "+f"(d[2]), "+f"(d[3])
        : "r"(a0), "r"(a1), "r"(a2), "r"(a3), "r"(b0), "r"(b1));
}
#define LDSM4(R0, R1, R2, R3, ADDR) \
    asm volatile("ldmatrix.sync.aligned.m8n8.x4.shared.b16 {%0,%1,%2,%3}, [%4];" \
        : "=r"(R0), "=r"(R1), "=r"(R2), "=r"(R3) : "r"(ADDR))
__device__ __forceinline__ void cp16(uint32_t dst, const void* src) {
    asm volatile("cp.async.cg.shared.global [%0], [%1], 16;" :: "r"(dst), "l"(src));
}
#define CP_COMMIT() asm volatile("cp.async.commit_group;" ::: "memory")
#define CP_WAIT0()  asm volatile("cp.async.wait_group 0;" ::: "memory")

// ---------------------------------------------------------------------------
__global__ void precompute_kernel(const float* __restrict__ wq,
                                  const float* __restrict__ wk,
                                  const float* __restrict__ wv,
                                  const float* __restrict__ wo) {
    int g = blockIdx.x * blockDim.x + threadIdx.x;   // 0..65535
    const float invs = 0.17677669529663689f;         // 1/sqrt(32)
    if (g < 32768) {            // P^T [n][c]
        int n = g >> 7, c = g & 127;
        int h = n >> 6, ct = n & 63;
        float s = 0.f;
#pragma unroll
        for (int d = 0; d < 32; d++)
            s += wq[c * 128 + h * 32 + d] * wk[ct * 128 + h * 32 + d];
        g_Phi[n * 128 + c] = __float2half_rn(s * invs);
    } else {                    // Wf^T [c2][n]
        int gg = g - 32768;
        int c2 = gg >> 8, n = gg & 255;
        int h = n >> 6, ct = n & 63;
        float s = 0.f;
#pragma unroll
        for (int d = 0; d < 32; d++)
            s += wv[ct * 128 + h * 32 + d] * wo[(h * 32 + d) * 128 + c2];
        g_Whi[c2 * 256 + n] = __float2half_rn(s);
    }
}

// ---------------------------------------------------------------------------
__global__ void __launch_bounds__(256, 1)
attn_kernel(const float* __restrict__ tg, const float* __restrict__ z,
            const float* __restrict__ tmask, const float* __restrict__ bo,
            float* __restrict__ out) {
    extern __shared__ char sm[];
    const uint32_t smb = smem_u32(sm);
    float* s_bo   = reinterpret_cast<float*>(sm + OFF_BO);
    float* s_bias = reinterpret_cast<float*>(sm + OFF_BIAS);

    const int tid = threadIdx.x;
    const int lane = tid & 31, w = tid >> 5;
    const int c4 = lane & 3, lr = lane >> 2;
    const int mi = w >> 2;          // 32-pixel band: mi*32 .. +32
    const int hd = w & 3;           // head (G1) / c2-band (G2)
    const int P0 = blockIdx.x * 64;

    // ---- stage B1 chunk 0 (k 0..63) via cp.async ----
#pragma unroll
    for (int it = 0; it < 8; it++) {
        int idx = tid + it * 256;
        int n = idx >> 3, i = idx & 7;
        cp16(smb + OFF_B + (uint32_t)n * B1_PITCH + i * 16,
             (const char*)(g_Phi + n * 128 + i * 8));
    }
    CP_COMMIT();

    // ---- bo, bias ----
    if (tid < 32) reinterpret_cast<float4*>(s_bo)[tid] =
        reinterpret_cast<const float4*>(bo)[tid];
    if (tid < 4) s_bias[tid] = INF_ * (tmask[tid] - 1.0f);

    // ---- stage z -> A1 fp16 ----
    {
        const float4* z4 = reinterpret_cast<const float4*>(z + (size_t)P0 * 128);
#pragma unroll
        for (int it = 0; it < 8; it++) {
            int e = tid + it * 256;
            float4 v = z4[e];
            int pix = e >> 5, q = e & 31;
            __half2 h0 = __floats2half2_rn(v.x, v.y);
            __half2 h1 = __floats2half2_rn(v.z, v.w);
            *reinterpret_cast<uint2*>(sm + OFF_A + pix * A1_PITCH + 8 * q) =
                make_uint2(*reinterpret_cast<uint32_t*>(&h0),
                           *reinterpret_cast<uint32_t*>(&h1));
        }
    }
    // ---- stage t -> fp16 smem (row = tt*64+pix, 128B data, pitch 144) ----
    {
        const float4* t4 = reinterpret_cast<const float4*>(tg);
#pragma unroll
        for (int it = 0; it < 16; it++) {
            int e = tid + it * 256;
            int row = e >> 4, i = e & 15;
            float4 v = t4[((size_t)(row >> 6) * NPIX + (size_t)(P0 + (row & 63))) * 16 + i];
            __half2 h0 = __floats2half2_rn(v.x, v.y);
            __half2 h1 = __floats2half2_rn(v.z, v.w);
            *reinterpret_cast<uint2*>(sm + OFF_T + row * T_PITCH + i * 8) =
                make_uint2(*reinterpret_cast<uint32_t*>(&h0),
                           *reinterpret_cast<uint32_t*>(&h1));
        }
    }

    // ---- fragment base addresses ----
    const uint32_t bRow  = ((lane >> 4) << 3) + (lane & 7);
    const uint32_t bKoff = ((lane >> 3) & 1) << 4;
    const uint32_t aA1 = smb + OFF_A + (mi * 32 + (lane & 15)) * A1_PITCH + (lane >> 4) * 16;
    const uint32_t aB1 = smb + OFF_B + (hd * 64 + bRow) * B1_PITCH + bKoff;

    // ---- GEMM1: warp tile 32x64; 2 k-chunks (64 each), double-buffered B ----
    float acc1[2][8][4] = {};
#pragma unroll 1
    for (int c = 0; c < 2; c++) {
        CP_WAIT0();
        __syncthreads();
        if (c == 0) {            // prefetch B1 chunk1
#pragma unroll
            for (int it = 0; it < 8; it++) {
                int idx = tid + it * 256;
                int n = idx >> 3, i = idx & 7;
                cp16(smb + OFF_B + B_BUF + (uint32_t)n * B1_PITCH + i * 16,
                     (const char*)(g_Phi + n * 128 + 64 + i * 8));
            }
        } else {                 // prefetch B2 chunk0 into buf0
#pragma unroll
            for (int it = 0; it < 8; it++) {
                int idx = tid + it * 256;
                int c2 = idx >> 4, i = idx & 15;
                cp16(smb + OFF_B + (uint32_t)c2 * B2_PITCH + i * 16,
                     (const char*)(g_Whi + c2 * 256 + i * 8));
            }
        }
        CP_COMMIT();
#pragma unroll
        for (int kk = 0; kk < 4; kk++) {
            const uint32_t ka = c * 128 + kk * 32;
            uint32_t a0[4], a1[4];
            LDSM4(a0[0], a0[1], a0[2], a0[3], aA1 + ka);
            LDSM4(a1[0], a1[1], a1[2], a1[3], aA1 + 16 * A1_PITCH + ka);
#pragma unroll
            for (int g = 0; g < 4; g++) {
                uint32_t b0, b1, b2, b3;
                LDSM4(b0, b1, b2, b3, aB1 + c * B_BUF + g * (16 * B1_PITCH) + kk * 32);
                mma16816(acc1[0][2 * g],     a0[0], a0[1], a0[2], a0[3], b0, b1);
                mma16816(acc1[0][2 * g + 1], a0[0], a0[1], a0[2], a0[3], b2, b3);
                mma16816(acc1[1][2 * g],     a1[0], a1[1], a1[2], a1[3], b0, b1);
                mma16816(acc1[1][2 * g + 1], a1[0], a1[1], a1[2], a1[3], b2, b3);
            }
        }
    }
    __syncthreads();   // all G1 fragment reads done before A2 overwrites A1

    // ---- epilogue: per 8-row group; t cached in regs, used for logits + M2 ----
#pragma unroll
    for (int a = 0; a < 4; a++) {
        const int mp = a >> 1, ah = a & 1;
        const int r = mi * 32 + mp * 16 + 8 * ah + lr;
        // cache t row segment: 8 np x 4 tt half2
        uint32_t tc[8][4];
#pragma unroll
        for (int np = 0; np < 8; np++) {
            const char* tb = sm + OFF_T + r * T_PITCH + (np * 8 + 2 * c4) * 2;
#pragma unroll
            for (int tt = 0; tt < 4; tt++)
                tc[np][tt] = *reinterpret_cast<const uint32_t*>(tb + tt * 64 * T_PITCH);
        }
        float lg0 = 0.f, lg1 = 0.f, lg2 = 0.f, lg3 = 0.f;
#pragma unroll
        for (int np = 0; np < 8; np++) {
            float d0 = acc1[mp][np][2 * ah], d1 = acc1[mp][np][2 * ah + 1];
            float2 f0 = __half22float2(*reinterpret_cast<__half2*>(&tc[np][0]));
            float2 f1 = __half22float2(*reinterpret_cast<__half2*>(&tc[np][1]));
            float2 f2 = __half22float2(*reinterpret_cast<__half2*>(&tc[np][2]));
            float2 f3 = __half22float2(*reinterpret_cast<__half2*>(&tc[np][3]));
            lg0 += d0 * f0.x + d1 * f0.y;
            lg1 += d0 * f1.x + d1 * f1.y;
            lg2 += d0 * f2.x + d1 * f2.y;
            lg3 += d0 * f3.x + d1 * f3.y;
        }
        lg0 += __shfl_xor_sync(~0u, lg0, 1); lg0 += __shfl_xor_sync(~0u, lg0, 2);
        lg1 += __shfl_xor_sync(~0u, lg1, 1); lg1 += __shfl_xor_sync(~0u, lg1, 2);
        lg2 += __shfl_xor_sync(~0u, lg2, 1); lg2 += __shfl_xor_sync(~0u, lg2, 2);
        lg3 += __shfl_xor_sync(~0u, lg3, 1); lg3 += __shfl_xor_sync(~0u, lg3, 2);
        lg0 += s_bias[0]; lg1 += s_bias[1]; lg2 += s_bias[2]; lg3 += s_bias[3];
        float m = fmaxf(fmaxf(lg0, lg1), fmaxf(lg2, lg3));
        float e0 = __expf(lg0 - m), e1 = __expf(lg1 - m);
        float e2 = __expf(lg2 - m), e3 = __expf(lg3 - m);
        float inv = 1.f / (e0 + e1 + e2 + e3);
        float at0 = e0 * inv, at1 = e1 * inv, at2 = e2 * inv, at3 = e3 * inv;
        // M2 build -> A2 (fp16), reusing cached t
#pragma unroll
        for (int np = 0; np < 8; np++) {
            float2 f0 = __half22float2(*reinterpret_cast<__half2*>(&tc[np][0]));
            float2 f1 = __half22float2(*reinterpret_cast<__half2*>(&tc[np][1]));
            float2 f2 = __half22float2(*reinterpret_cast<__half2*>(&tc[np][2]));
            float2 f3 = __half22float2(*reinterpret_cast<__half2*>(&tc[np][3]));
            float m0 = at0 * f0.x + at1 * f1.x + at2 * f2.x + at3 * f3.x;
            float m1 = at0 * f0.y + at1 * f1.y + at2 * f2.y + at3 * f3.y;
            __half2 h = __floats2half2_rn(m0, m1);
            *reinterpret_cast<uint32_t*>(
                sm + OFF_A + r * A2_PITCH + (hd * 64 + np * 8 + 2 * c4) * 2) =
                *reinterpret_cast<uint32_t*>(&h);
        }
    }

    // ---- GEMM2: warp tile 32x32; 2 k-chunks (128 each), double-buffered ----
    const uint32_t aA2 = smb + OFF_A + (mi * 32 + (lane & 15)) * A2_PITCH + (lane >> 4) * 16;
    const uint32_t aB2 = smb + OFF_B + (hd * 32 + bRow) * B2_PITCH + bKoff;
    float acc2[2][4][4] = {};
#pragma unroll 1
    for (int c = 0; c < 2; c++) {
        CP_WAIT0();
        __syncthreads();         // c==0: also publishes A2 everywhere
        if (c == 0) {
#pragma unroll
            for (int it = 0; it < 8; it++) {
                int idx = tid + it * 256;
                int c2 = idx >> 4, i = idx & 15;
                cp16(smb + OFF_B + B_BUF + (uint32_t)c2 * B2_PITCH + i * 16,
                     (const char*)(g_Whi + c2 * 256 + 128 + i * 8));
            }
            CP_COMMIT();
        }
#pragma unroll
        for (int kk = 0; kk < 8; kk++) {
            const uint32_t ka = c * 256 + kk * 32;
            uint32_t a0[4], a1[4];
            LDSM4(a0[0], a0[1], a0[2], a0[3], aA2 + ka);
            LDSM4(a1[0], a1[1], a1[2], a1[3], aA2 + 16 * A2_PITCH + ka);
#pragma unroll
            for (int g = 0; g < 2; g++) {
                uint32_t b0, b1, b2, b3;
                LDSM4(b0, b1, b2, b3, aB2 + c * B_BUF + g * (16 * B2_PITCH) + kk * 32);
                mma16816(acc2[0][2 * g],     a0[0], a0[1], a0[2], a0[3], b0, b1);
                mma16816(acc2[0][2 * g + 1], a0[0], a0[1], a0[2], a0[3], b2, b3);
                mma16816(acc2[1][2 * g],     a1[0], a1[1], a1[2], a1[3], b0, b1);
                mma16816(acc2[1][2 * g + 1], a1[0], a1[1], a1[2], a1[3], b2, b3);
            }
        }
    }

    // ---- output: add bias, STG.64 ----
#pragma unroll
    for (int mp = 0; mp < 2; mp++)
#pragma unroll
        for (int ah = 0; ah < 2; ah++) {
            const size_t r = (size_t)(P0 + mi * 32 + mp * 16 + 8 * ah + lr);
#pragma unroll
            for (int np = 0; np < 4; np++) {
                const int col = hd * 32 + np * 8 + 2 * c4;
                float2 b = *reinterpret_cast<const float2*>(s_bo + col);
                float2 v;
                v.x = acc2[mp][np][2 * ah] + b.x;
                v.y = acc2[mp][np][2 * ah + 1] + b.y;
                *reinterpret_cast<float2*>(out + r * 128 + col) = v;
            }
        }
}

// ---------------------------------------------------------------------------
extern "C" void kernel_launch(void* const* d_in, const int* in_sizes, int n_in,
                              void* d_out, int out_size) {
    const float* t     = (const float*)d_in[0];
    const float* z     = (const float*)d_in[1];
    const float* tmask = (const float*)d_in[2];
    const float* wq    = (const float*)d_in[3];
    const float* wk    = (const float*)d_in[4];
    const float* wv    = (const float*)d_in[5];
    const float* wo    = (const float*)d_in[6];
    const float* bo    = (const float*)d_in[7];
    float* out = (float*)d_out;

    cudaFuncSetAttribute(attn_kernel, cudaFuncAttributeMaxDynamicSharedMemorySize,
                         (int)SMEM_TOTAL);
    precompute_kernel<<<256, 256>>>(wq, wk, wv, wo);
    attn_kernel<<<NPIX / 64, 256, SMEM_TOTAL>>>(t, z, tmask, bo, out);
}

// round 11
// speedup vs baseline: 4.8854x; 1.1993x over previous
#include <cuda_runtime.h>
#include <cuda_fp16.h>
#include <cstdint>

// ---------------------------------------------------------------------------
// TemplatePointwiseAttention via mma.sync.m16n8k16, all-fp16 operands
// (fp32 accum), ldmatrix.x4, cp.async double-buffered B.
// R11: 2 CTAs/SM (smem 110KB, regs capped 128), B chunks halved
//      (B1 k=32 pitch 80, B2 k=64 pitch 144), epilogue reads t twice (no
//      register t-cache). Warp tiles G1 32x64 / G2 32x32 (B-frag reuse).
// Warp (mi,hd): mi=w>>2 in {0,1} (32-pixel band), hd=w&3 (head / c2 band).
// ---------------------------------------------------------------------------

#define NPIX (512*512)
#define INF_ 100000.0f

// smem byte layout (110 KB total -> 2 CTAs/SM)
#define OFF_BO   0u
#define OFF_BIAS 512u
#define OFF_A    1024u
#define A1_PITCH 272u        // 64 rows x 256B fp16 z; 68 words == 4 mod 32
#define A2_PITCH 528u        // 64 rows x 512B fp16 M2; 132 words == 4 mod 32
#define OFF_B    34816u      // two 20480B buffers
#define B_BUF    20480u
#define B1_PITCH 80u         // 256 rows x 64B (k=32 chunk); 20 words: CF
#define B2_PITCH 144u        // 128 rows x 128B (k=64 chunk); 36 words: CF
#define OFF_T    75776u
#define T_PITCH  144u        // 256 rows x 128B fp16 t
#define SMEM_TOTAL 112640u

__device__ __align__(16) __half g_Phi[256 * 128];  // [n][c]   fp16
__device__ __align__(16) __half g_Whi[128 * 256];  // [c2][n]  fp16

__device__ __forceinline__ uint32_t smem_u32(const void* p) {
    uint32_t a;
    asm("{ .reg .u64 t; cvta.to.shared.u64 t, %1; cvt.u32.u64 %0, t; }" : "=r"(a) : "l"(p));
    return a;
}
__device__ __forceinline__ void mma16816(float* d, uint32_t a0, uint32_t a1,
                                         uint32_t a2, uint32_t a3,
                                         uint32_t b0, uint32_t b1) {
    asm volatile(
        "mma.sync.aligned.m16n8k16.row.col.f32.f16.f16.f32 "
        "{%0,%1,%2,%3}, {%4,%5,%6,%7}, {%8,%9}, {%0,%1,%2,%3};"
        : "+f"(d[0]), "+f"(d[1]), "+f"(d[2]), "+f"(d[3])
        : "r"(a0), "r"(a1), "r"(a2), "r"(a3), "r"(b0), "r"(b1));
}
#define LDSM4(R0, R1, R2, R3, ADDR) \
    asm volatile("ldmatrix.sync.aligned.m8n8.x4.shared.b16 {%0,%1,%2,%3}, [%4];" \
        : "=r"(R0), "=r"(R1), "=r"(R2), "=r"(R3) : "r"(ADDR))
__device__ __forceinline__ void cp16(uint32_t dst, const void* src) {
    asm volatile("cp.async.cg.shared.global [%0], [%1], 16;" :: "r"(dst), "l"(src));
}
#define CP_COMMIT() asm volatile("cp.async.commit_group;" ::: "memory")
#define CP_WAIT0()  asm volatile("cp.async.wait_group 0;" ::: "memory")

// ---------------------------------------------------------------------------
__global__ void precompute_kernel(const float* __restrict__ wq,
                                  const float* __restrict__ wk,
                                  const float* __restrict__ wv,
                                  const float* __restrict__ wo) {
    int g = blockIdx.x * blockDim.x + threadIdx.x;   // 0..65535
    const float invs = 0.17677669529663689f;         // 1/sqrt(32)
    if (g < 32768) {            // P^T [n][c]
        int n = g >> 7, c = g & 127;
        int h = n >> 6, ct = n & 63;
        float s = 0.f;
#pragma unroll
        for (int d = 0; d < 32; d++)
            s += wq[c * 128 + h * 32 + d] * wk[ct * 128 + h * 32 + d];
        g_Phi[n * 128 + c] = __float2half_rn(s * invs);
    } else {                    // Wf^T [c2][n]
        int gg = g - 32768;
        int c2 = gg >> 8, n = gg & 255;
        int h = n >> 6, ct = n & 63;
        float s = 0.f;
#pragma unroll
        for (int d = 0; d < 32; d++)
            s += wv[ct * 128 + h * 32 + d] * wo[(h * 32 + d) * 128 + c2];
        g_Whi[c2 * 256 + n] = __float2half_rn(s);
    }
}

// ---------------------------------------------------------------------------
__global__ void __launch_bounds__(256, 2)
attn_kernel(const float* __restrict__ tg, const float* __restrict__ z,
            const float* __restrict__ tmask, const float* __restrict__ bo,
            float* __restrict__ out) {
    extern __shared__ char sm[];
    const uint32_t smb = smem_u32(sm);
    float* s_bo   = reinterpret_cast<float*>(sm + OFF_BO);
    float* s_bias = reinterpret_cast<float*>(sm + OFF_BIAS);

    const int tid = threadIdx.x;
    const int lane = tid & 31, w = tid >> 5;
    const int c4 = lane & 3, lr = lane >> 2;
    const int mi = w >> 2;          // 32-pixel band: mi*32 .. +32
    const int hd = w & 3;           // head (G1) / c2-band (G2)
    const int P0 = blockIdx.x * 64;

    // ---- stage B1 chunk 0 (k 0..31) via cp.async ----
#pragma unroll
    for (int it = 0; it < 4; it++) {
        int idx = tid + it * 256;
        int n = idx >> 2, i = idx & 3;
        cp16(smb + OFF_B + (uint32_t)n * B1_PITCH + i * 16,
             (const char*)(g_Phi + n * 128 + i * 8));
    }
    CP_COMMIT();

    // ---- bo, bias ----
    if (tid < 32) reinterpret_cast<float4*>(s_bo)[tid] =
        reinterpret_cast<const float4*>(bo)[tid];
    if (tid < 4) s_bias[tid] = INF_ * (tmask[tid] - 1.0f);

    // ---- stage z -> A1 fp16 ----
    {
        const float4* z4 = reinterpret_cast<const float4*>(z + (size_t)P0 * 128);
#pragma unroll
        for (int it = 0; it < 8; it++) {
            int e = tid + it * 256;
            float4 v = z4[e];
            int pix = e >> 5, q = e & 31;
            __half2 h0 = __floats2half2_rn(v.x, v.y);
            __half2 h1 = __floats2half2_rn(v.z, v.w);
            *reinterpret_cast<uint2*>(sm + OFF_A + pix * A1_PITCH + 8 * q) =
                make_uint2(*reinterpret_cast<uint32_t*>(&h0),
                           *reinterpret_cast<uint32_t*>(&h1));
        }
    }
    // ---- stage t -> fp16 smem (row = tt*64+pix, 128B data, pitch 144) ----
    {
        const float4* t4 = reinterpret_cast<const float4*>(tg);
#pragma unroll
        for (int it = 0; it < 16; it++) {
            int e = tid + it * 256;
            int row = e >> 4, i = e & 15;
            float4 v = t4[((size_t)(row >> 6) * NPIX + (size_t)(P0 + (row & 63))) * 16 + i];
            __half2 h0 = __floats2half2_rn(v.x, v.y);
            __half2 h1 = __floats2half2_rn(v.z, v.w);
            *reinterpret_cast<uint2*>(sm + OFF_T + row * T_PITCH + i * 8) =
                make_uint2(*reinterpret_cast<uint32_t*>(&h0),
                           *reinterpret_cast<uint32_t*>(&h1));
        }
    }

    // ---- fragment base addresses ----
    const uint32_t bRow  = ((lane >> 4) << 3) + (lane & 7);
    const uint32_t bKoff = ((lane >> 3) & 1) << 4;
    const uint32_t aA1 = smb + OFF_A + (mi * 32 + (lane & 15)) * A1_PITCH + (lane >> 4) * 16;
    const uint32_t aB1 = smb + OFF_B + (hd * 64 + bRow) * B1_PITCH + bKoff;

    // ---- GEMM1: warp tile 32x64; 4 k-chunks (32 each), double-buffered B ----
    float acc1[2][8][4] = {};
#pragma unroll 1
    for (int c = 0; c < 4; c++) {
        CP_WAIT0();
        __syncthreads();
        if (c < 3) {             // prefetch B1 chunk c+1
#pragma unroll
            for (int it = 0; it < 4; it++) {
                int idx = tid + it * 256;
                int n = idx >> 2, i = idx & 3;
                cp16(smb + OFF_B + (uint32_t)(((c + 1) & 1) * B_BUF) +
                         (uint32_t)n * B1_PITCH + i * 16,
                     (const char*)(g_Phi + n * 128 + (c + 1) * 32 + i * 8));
            }
        } else {                 // prefetch B2 chunk0 into buf0
#pragma unroll
            for (int it = 0; it < 4; it++) {
                int idx = tid + it * 256;
                int c2 = idx >> 3, i = idx & 7;
                cp16(smb + OFF_B + (uint32_t)c2 * B2_PITCH + i * 16,
                     (const char*)(g_Whi + c2 * 256 + i * 8));
            }
        }
        CP_COMMIT();
#pragma unroll
        for (int kk = 0; kk < 2; kk++) {
            const uint32_t ka = (c * 2 + kk) * 32;
            uint32_t a0[4], a1[4];
            LDSM4(a0[0], a0[1], a0[2], a0[3], aA1 + ka);
            LDSM4(a1[0], a1[1], a1[2], a1[3], aA1 + 16 * A1_PITCH + ka);
#pragma unroll
            for (int g = 0; g < 4; g++) {
                uint32_t b0, b1, b2, b3;
                LDSM4(b0, b1, b2, b3,
                      aB1 + (c & 1) * B_BUF + g * (16 * B1_PITCH) + kk * 32);
                mma16816(acc1[0][2 * g],     a0[0], a0[1], a0[2], a0[3], b0, b1);
                mma16816(acc1[0][2 * g + 1], a0[0], a0[1], a0[2], a0[3], b2, b3);
                mma16816(acc1[1][2 * g],     a1[0], a1[1], a1[2], a1[3], b0, b1);
                mma16816(acc1[1][2 * g + 1], a1[0], a1[1], a1[2], a1[3], b2, b3);
            }
        }
    }
    __syncthreads();   // all G1 fragment reads done before A2 overwrites A1

    // ---- epilogue: logits + softmax + M2 (t read from smem twice) ----
#pragma unroll
    for (int a = 0; a < 4; a++) {
        const int mp = a >> 1, ah = a & 1;
        const int r = mi * 32 + mp * 16 + 8 * ah + lr;
        const char* tb0 = sm + OFF_T + r * T_PITCH + (2 * c4) * 2;
        float lg0 = 0.f, lg1 = 0.f, lg2 = 0.f, lg3 = 0.f;
#pragma unroll
        for (int np = 0; np < 8; np++) {
            float d0 = acc1[mp][np][2 * ah], d1 = acc1[mp][np][2 * ah + 1];
            const char* tb = tb0 + np * 16;
            float2 f0 = __half22float2(*reinterpret_cast<const __half2*>(tb));
            float2 f1 = __half22float2(*reinterpret_cast<const __half2*>(tb + 64 * T_PITCH));
            float2 f2 = __half22float2(*reinterpret_cast<const __half2*>(tb + 128 * T_PITCH));
            float2 f3 = __half22float2(*reinterpret_cast<const __half2*>(tb + 192 * T_PITCH));
            lg0 += d0 * f0.x + d1 * f0.y;
            lg1 += d0 * f1.x + d1 * f1.y;
            lg2 += d0 * f2.x + d1 * f2.y;
            lg3 += d0 * f3.x + d1 * f3.y;
        }
        lg0 += __shfl_xor_sync(~0u, lg0, 1); lg0 += __shfl_xor_sync(~0u, lg0, 2);
        lg1 += __shfl_xor_sync(~0u, lg1, 1); lg1 += __shfl_xor_sync(~0u, lg1, 2);
        lg2 += __shfl_xor_sync(~0u, lg2, 1); lg2 += __shfl_xor_sync(~0u, lg2, 2);
        lg3 += __shfl_xor_sync(~0u, lg3, 1); lg3 += __shfl_xor_sync(~0u, lg3, 2);
        lg0 += s_bias[0]; lg1 += s_bias[1]; lg2 += s_bias[2]; lg3 += s_bias[3];
        float m = fmaxf(fmaxf(lg0, lg1), fmaxf(lg2, lg3));
        float e0 = __expf(lg0 - m), e1 = __expf(lg1 - m);
        float e2 = __expf(lg2 - m), e3 = __expf(lg3 - m);
        float inv = 1.f / (e0 + e1 + e2 + e3);
        float at0 = e0 * inv, at1 = e1 * inv, at2 = e2 * inv, at3 = e3 * inv;
        // M2 build -> A2 (fp16); banks 4*lr+c4(+4np): conflict-free
#pragma unroll
        for (int np = 0; np < 8; np++) {
            const char* tb = tb0 + np * 16;
            float2 f0 = __half22float2(*reinterpret_cast<const __half2*>(tb));
            float2 f1 = __half22float2(*reinterpret_cast<const __half2*>(tb + 64 * T_PITCH));
            float2 f2 = __half22float2(*reinterpret_cast<const __half2*>(tb + 128 * T_PITCH));
            float2 f3 = __half22float2(*reinterpret_cast<const __half2*>(tb + 192 * T_PITCH));
            float m0 = at0 * f0.x + at1 * f1.x + at2 * f2.x + at3 * f3.x;
            float m1 = at0 * f0.y + at1 * f1.y + at2 * f2.y + at3 * f3.y;
            __half2 h = __floats2half2_rn(m0, m1);
            *reinterpret_cast<uint32_t*>(
                sm + OFF_A + r * A2_PITCH + (hd * 64 + np * 8 + 2 * c4) * 2) =
                *reinterpret_cast<uint32_t*>(&h);
        }
    }

    // ---- GEMM2: warp tile 32x32; 4 k-chunks (64 each), double-buffered ----
    const uint32_t aA2 = smb + OFF_A + (mi * 32 + (lane & 15)) * A2_PITCH + (lane >> 4) * 16;
    const uint32_t aB2 = smb + OFF_B + (hd * 32 + bRow) * B2_PITCH + bKoff;
    float acc2[2][4][4] = {};
#pragma unroll 1
    for (int kq = 0; kq < 4; kq++) {
        CP_WAIT0();
        __syncthreads();         // kq==0: also publishes A2 everywhere
        if (kq < 3) {
#pragma unroll
            for (int it = 0; it < 4; it++) {
                int idx = tid + it * 256;
                int c2 = idx >> 3, i = idx & 7;
                cp16(smb + OFF_B + (uint32_t)(((kq + 1) & 1) * B_BUF) +
                         (uint32_t)c2 * B2_PITCH + i * 16,
                     (const char*)(g_Whi + c2 * 256 + (kq + 1) * 64 + i * 8));
            }
            CP_COMMIT();
        }
#pragma unroll
        for (int kk = 0; kk < 4; kk++) {
            const uint32_t ka = (kq * 4 + kk) * 32;
            uint32_t a0[4], a1[4];
            LDSM4(a0[0], a0[1], a0[2], a0[3], aA2 + ka);
            LDSM4(a1[0], a1[1], a1[2], a1[3], aA2 + 16 * A2_PITCH + ka);
#pragma unroll
            for (int g = 0; g < 2; g++) {
                uint32_t b0, b1, b2, b3;
                LDSM4(b0, b1, b2, b3,
                      aB2 + (kq & 1) * B_BUF + g * (16 * B2_PITCH) + kk * 32);
                mma16816(acc2[0][2 * g],     a0[0], a0[1], a0[2], a0[3], b0, b1);
                mma16816(acc2[0][2 * g + 1], a0[0], a0[1], a0[2], a0[3], b2, b3);
                mma16816(acc2[1][2 * g],     a1[0], a1[1], a1[2], a1[3], b0, b1);
                mma16816(acc2[1][2 * g + 1], a1[0], a1[1], a1[2], a1[3], b2, b3);
            }
        }
    }

    // ---- output: add bias, STG.64 ----
#pragma unroll
    for (int mp = 0; mp < 2; mp++)
#pragma unroll
        for (int ah = 0; ah < 2; ah++) {
            const size_t r = (size_t)(P0 + mi * 32 + mp * 16 + 8 * ah + lr);
#pragma unroll
            for (int np = 0; np < 4; np++) {
                const int col = hd * 32 + np * 8 + 2 * c4;
                float2 b = *reinterpret_cast<const float2*>(s_bo + col);
                float2 v;
                v.x = acc2[mp][np][2 * ah] + b.x;
                v.y = acc2[mp][np][2 * ah + 1] + b.y;
                *reinterpret_cast<float2*>(out + r * 128 + col) = v;
            }
        }
}

// ---------------------------------------------------------------------------
extern "C" void kernel_launch(void* const* d_in, const int* in_sizes, int n_in,
                              void* d_out, int out_size) {
    const float* t     = (const float*)d_in[0];
    const float* z     = (const float*)d_in[1];
    const float* tmask = (const float*)d_in[2];
    const float* wq    = (const float*)d_in[3];
    const float* wk    = (const float*)d_in[4];
    const float* wv    = (const float*)d_in[5];
    const float* wo    = (const float*)d_in[6];
    const float* bo    = (const float*)d_in[7];
    float* out = (float*)d_out;

    cudaFuncSetAttribute(attn_kernel, cudaFuncAttributeMaxDynamicSharedMemorySize,
                         (int)SMEM_TOTAL);
    precompute_kernel<<<256, 256>>>(wq, wk, wv, wo);
    attn_kernel<<<NPIX / 64, 256, SMEM_TOTAL>>>(t, z, tmask, bo, out);
}